// round 1
// baseline (speedup 1.0000x reference)
#include <cuda_runtime.h>
#include <math.h>

// Problem constants
#define BB   4
#define NN   1024
#define NCC  77
#define DD   1024
#define HH   16
#define HDD  64
#define DFF_ 4096
#define STOT (NN + NCC)   // 1101
#define D6   (6 * DD)

// ---------------------------------------------------------------------------
// Scratch buffers (device globals — no allocations allowed)
// ---------------------------------------------------------------------------
__device__ float g_ada  [BB * D6];
__device__ float g_ada_c[BB * D6];
__device__ float g_xt   [BB * NN  * DD];
__device__ float g_ct   [BB * NCC * DD];
__device__ float g_qkv  [BB * NN  * 3 * DD];
__device__ float g_qkv_c[BB * NCC * 3 * DD];
__device__ float g_ax   [BB * NN  * DD];
__device__ float g_acnd [BB * NCC * DD];
__device__ float g_x1   [BB * NN  * DD];
__device__ float g_c1   [BB * NCC * DD];
__device__ float g_h    [BB * NN  * DFF_];
__device__ float g_hc   [BB * NCC * DFF_];

// ---------------------------------------------------------------------------
// adaLN: out[b, :] = silu(c[b, :]) @ W + bias       (B x 6144, K=1024)
// grid: (6144/256, B), block 256
// ---------------------------------------------------------------------------
__global__ void ada_kernel(const float* __restrict__ c, const float* __restrict__ W,
                           const float* __restrict__ bias, float* __restrict__ out)
{
    int b = blockIdx.y;
    int j = blockIdx.x * 256 + threadIdx.x;
    __shared__ float sc[DD];
    for (int k = threadIdx.x; k < DD; k += 256) {
        float v = c[b * DD + k];
        sc[k] = v / (1.0f + expf(-v));
    }
    __syncthreads();
    float acc = bias[j];
#pragma unroll 8
    for (int k = 0; k < DD; k++)
        acc += sc[k] * W[(size_t)k * D6 + j];
    out[b * D6 + j] = acc;
}

// ---------------------------------------------------------------------------
// LayerNorm (eps=1e-6, no affine) + modulate: (x-mu)*inv*(1+scale) + shift
// grid: B*tokens blocks, block 256.  D=1024 -> 4 elems/thread.
// ---------------------------------------------------------------------------
__global__ void ln_mod_kernel(const float* __restrict__ x, const float* __restrict__ ada,
                              float* __restrict__ out, int tokens, int sh_off, int sc_off)
{
    int row = blockIdx.x;
    int b = row / tokens;
    const float* xr = x + (size_t)row * DD;

    float v[4];
    float s = 0.f, s2 = 0.f;
#pragma unroll
    for (int i = 0; i < 4; i++) {
        v[i] = xr[threadIdx.x + i * 256];
        s += v[i];
        s2 += v[i] * v[i];
    }
#pragma unroll
    for (int o = 16; o; o >>= 1) {
        s  += __shfl_xor_sync(0xffffffffu, s, o);
        s2 += __shfl_xor_sync(0xffffffffu, s2, o);
    }
    __shared__ float ss[8], ss2[8];
    int w = threadIdx.x >> 5, ln = threadIdx.x & 31;
    if (ln == 0) { ss[w] = s; ss2[w] = s2; }
    __syncthreads();
    float S = 0.f, S2 = 0.f;
#pragma unroll
    for (int i = 0; i < 8; i++) { S += ss[i]; S2 += ss2[i]; }
    float mu  = S * (1.0f / DD);
    float var = S2 * (1.0f / DD) - mu * mu;
    float inv = rsqrtf(var + 1e-6f);

    const float* adab = ada + (size_t)b * D6;
#pragma unroll
    for (int i = 0; i < 4; i++) {
        int j = threadIdx.x + i * 256;
        out[(size_t)row * DD + j] = (v[i] - mu) * inv * (1.0f + adab[sc_off + j]) + adab[sh_off + j];
    }
}

// ---------------------------------------------------------------------------
// Tiled SGEMM: C[M,Nn] = A[M,K] @ W[K,Nn] + bias, with epilogue modes:
//   MODE 0: bias only
//   MODE 1: gelu(tanh approx)
//   MODE 2: res + gate * (.)   where gate = ada[b*6D + gate_off + col], b=row/tokens
// BM=BN=128, BK=8, 256 threads, 8x8 per thread. Nn must be a multiple of 128
// (3072/1024/4096 all are); M is guarded.
// ---------------------------------------------------------------------------
template <int MODE>
__global__ void __launch_bounds__(256)
gemm_kernel(const float* __restrict__ A, const float* __restrict__ W,
            const float* __restrict__ bias, const float* __restrict__ res,
            const float* __restrict__ ada, int gate_off,
            float* __restrict__ C, int M, int K, int Nn, int tokens)
{
    __shared__ float As[8][128];
    __shared__ float Bs[8][128];

    int bm = blockIdx.y * 128, bn = blockIdx.x * 128;
    int tid = threadIdx.x;
    int tx = tid & 15, ty = tid >> 4;

    float acc[8][8];
#pragma unroll
    for (int i = 0; i < 8; i++)
#pragma unroll
        for (int j = 0; j < 8; j++) acc[i][j] = 0.f;

    int ar = tid >> 1;            // 0..127
    int acc4 = (tid & 1) << 2;    // 0 or 4
    int br = tid >> 5;            // 0..7
    int bc = (tid & 31) << 2;     // 0..124

    for (int k0 = 0; k0 < K; k0 += 8) {
        float4 av;
        if (bm + ar < M) av = *(const float4*)(A + (size_t)(bm + ar) * K + k0 + acc4);
        else             av = make_float4(0.f, 0.f, 0.f, 0.f);
        As[acc4 + 0][ar] = av.x; As[acc4 + 1][ar] = av.y;
        As[acc4 + 2][ar] = av.z; As[acc4 + 3][ar] = av.w;

        float4 bv = *(const float4*)(W + (size_t)(k0 + br) * Nn + bn + bc);
        *(float4*)&Bs[br][bc] = bv;
        __syncthreads();

#pragma unroll
        for (int kk = 0; kk < 8; kk++) {
            float4 a0 = *(float4*)&As[kk][ty * 8];
            float4 a1 = *(float4*)&As[kk][ty * 8 + 4];
            float4 b0 = *(float4*)&Bs[kk][tx * 8];
            float4 b1 = *(float4*)&Bs[kk][tx * 8 + 4];
            float a[8] = {a0.x, a0.y, a0.z, a0.w, a1.x, a1.y, a1.z, a1.w};
            float bb[8] = {b0.x, b0.y, b0.z, b0.w, b1.x, b1.y, b1.z, b1.w};
#pragma unroll
            for (int i = 0; i < 8; i++)
#pragma unroll
                for (int j = 0; j < 8; j++) acc[i][j] += a[i] * bb[j];
        }
        __syncthreads();
    }

#pragma unroll
    for (int i = 0; i < 8; i++) {
        int row = bm + ty * 8 + i;
        if (row >= M) continue;
        int b = row / tokens;
        size_t rbase = (size_t)row * Nn;
#pragma unroll
        for (int j = 0; j < 8; j++) {
            int col = bn + tx * 8 + j;
            float v = acc[i][j] + bias[col];
            if (MODE == 1) {
                float t = 0.7978845608028654f * (v + 0.044715f * v * v * v);
                v = 0.5f * v * (1.0f + tanhf(t));
            } else if (MODE == 2) {
                v = res[rbase + col] + ada[(size_t)b * D6 + gate_off + col] * v;
            }
            C[rbase + col] = v;
        }
    }
}

// ---------------------------------------------------------------------------
// Attention: full softmax over S=1101 (x tokens ++ cond tokens), per (b,h).
// Block: 256 threads = 8 warps; 1 warp per query (online softmax).
// K chunk stored transposed [d][key] with +1 pad -> conflict-free score reads.
// grid: (ceil(1101/8), 16, 4)
// ---------------------------------------------------------------------------
#define QT 8
#define CK 64

__global__ void __launch_bounds__(256)
attn_kernel(const float* __restrict__ qkv, const float* __restrict__ qkv_c,
            float* __restrict__ out_x, float* __restrict__ out_c)
{
    int b = blockIdx.z, h = blockIdx.y;
    int q0 = blockIdx.x * QT;
    int tid = threadIdx.x;
    int warp = tid >> 5, lane = tid & 31;

    __shared__ float q_s[QT][HDD];       // 2 KB
    __shared__ float k_s[HDD][CK + 1];   // 16.6 KB (transposed, padded)
    __shared__ float v_s[CK][HDD];       // 16 KB
    __shared__ float p_s[QT][CK];        // 2 KB

    // load Q tile (scaled by HD^-0.5 = 0.125)
    for (int idx = tid; idx < QT * HDD; idx += 256) {
        int qi = idx / HDD, d = idx % HDD;
        int s = q0 + qi;
        float val = 0.f;
        if (s < STOT) {
            if (s < NN) val = qkv[((size_t)(b * NN + s)) * 3072 + h * 64 + d];
            else        val = qkv_c[((size_t)(b * NCC + (s - NN))) * 3072 + h * 64 + d];
        }
        q_s[qi][d] = val * 0.125f;
    }
    __syncthreads();

    float m = -INFINITY, l = 0.f;
    float o0 = 0.f, o1 = 0.f;   // dims lane, lane+32
    int myq = q0 + warp;

    for (int kc = 0; kc < STOT; kc += CK) {
        // cooperative load of K (transposed) and V chunk
        for (int idx = tid; idx < CK * HDD; idx += 256) {
            int kk = idx / HDD, d = idx % HDD;
            int s = kc + kk;
            float kv = 0.f, vv = 0.f;
            if (s < STOT) {
                const float* src;
                size_t base;
                if (s < NN) { src = qkv;   base = ((size_t)(b * NN + s)) * 3072; }
                else        { src = qkv_c; base = ((size_t)(b * NCC + (s - NN))) * 3072; }
                kv = src[base + 1024 + h * 64 + d];
                vv = src[base + 2048 + h * 64 + d];
            }
            k_s[d][kk] = kv;
            v_s[kk][d] = vv;
        }
        __syncthreads();

        int nk = STOT - kc; if (nk > CK) nk = CK;

        // scores: each lane handles keys (lane) and (lane+32)
        float s0 = 0.f, s1 = 0.f;
#pragma unroll 8
        for (int d = 0; d < HDD; d++) {
            float qv = q_s[warp][d];
            s0 += qv * k_s[d][lane];
            s1 += qv * k_s[d][lane + 32];
        }
        if (lane      >= nk) s0 = -INFINITY;
        if (lane + 32 >= nk) s1 = -INFINITY;

        // online softmax update
        float mloc = fmaxf(s0, s1);
#pragma unroll
        for (int o = 16; o; o >>= 1) mloc = fmaxf(mloc, __shfl_xor_sync(0xffffffffu, mloc, o));
        float mnew = fmaxf(m, mloc);
        float corr = __expf(m - mnew);
        float p0 = __expf(s0 - mnew);
        float p1 = __expf(s1 - mnew);
        float psum = p0 + p1;
#pragma unroll
        for (int o = 16; o; o >>= 1) psum += __shfl_xor_sync(0xffffffffu, psum, o);
        l = l * corr + psum;
        o0 *= corr; o1 *= corr;
        m = mnew;

        p_s[warp][lane] = p0;
        p_s[warp][lane + 32] = p1;
        __syncwarp();

        // P @ V
#pragma unroll 4
        for (int k2 = 0; k2 < CK; k2++) {
            float p = p_s[warp][k2];
            o0 += p * v_s[k2][lane];
            o1 += p * v_s[k2][lane + 32];
        }
        __syncthreads();
    }

    if (myq < STOT) {
        float invl = 1.0f / l;
        o0 *= invl; o1 *= invl;
        if (myq < NN) {
            float* o = out_x + ((size_t)(b * NN + myq)) * DD + h * 64;
            o[lane] = o0; o[lane + 32] = o1;
        } else {
            float* o = out_c + ((size_t)(b * NCC + (myq - NN))) * DD + h * 64;
            o[lane] = o0; o[lane + 32] = o1;
        }
    }
}

// ---------------------------------------------------------------------------
// Launch orchestration
// ---------------------------------------------------------------------------
extern "C" void kernel_launch(void* const* d_in, const int* in_sizes, int n_in,
                              void* d_out, int out_size)
{
    const float* x       = (const float*)d_in[0];
    const float* cond    = (const float*)d_in[1];
    const float* c       = (const float*)d_in[2];
    const float* W_ada   = (const float*)d_in[3];
    const float* b_ada   = (const float*)d_in[4];
    const float* W_ada_c = (const float*)d_in[5];
    const float* b_ada_c = (const float*)d_in[6];
    const float* W_qkv   = (const float*)d_in[7];
    const float* b_qkv   = (const float*)d_in[8];
    const float* W_proj  = (const float*)d_in[9];
    const float* b_proj  = (const float*)d_in[10];
    const float* W_qkv_c = (const float*)d_in[11];
    const float* b_qkv_c = (const float*)d_in[12];
    const float* W_proj_c= (const float*)d_in[13];
    const float* b_proj_c= (const float*)d_in[14];
    const float* W_fc1   = (const float*)d_in[15];
    const float* b_fc1   = (const float*)d_in[16];
    const float* W_fc2   = (const float*)d_in[17];
    const float* b_fc2   = (const float*)d_in[18];
    const float* W_fc1_c = (const float*)d_in[19];
    const float* b_fc1_c = (const float*)d_in[20];
    const float* W_fc2_c = (const float*)d_in[21];
    const float* b_fc2_c = (const float*)d_in[22];

    float* out   = (float*)d_out;
    float* out_x = out;
    float* out_c = out + (size_t)BB * NN * DD;

    float *ada, *ada_c, *xt, *ct, *qkv, *qkv_c, *ax, *acnd, *x1, *c1, *hb, *hbc;
    cudaGetSymbolAddress((void**)&ada,   g_ada);
    cudaGetSymbolAddress((void**)&ada_c, g_ada_c);
    cudaGetSymbolAddress((void**)&xt,    g_xt);
    cudaGetSymbolAddress((void**)&ct,    g_ct);
    cudaGetSymbolAddress((void**)&qkv,   g_qkv);
    cudaGetSymbolAddress((void**)&qkv_c, g_qkv_c);
    cudaGetSymbolAddress((void**)&ax,    g_ax);
    cudaGetSymbolAddress((void**)&acnd,  g_acnd);
    cudaGetSymbolAddress((void**)&x1,    g_x1);
    cudaGetSymbolAddress((void**)&c1,    g_c1);
    cudaGetSymbolAddress((void**)&hb,    g_h);
    cudaGetSymbolAddress((void**)&hbc,   g_hc);

    const int M  = BB * NN;    // 4096
    const int Mc = BB * NCC;   // 308

    // 1) adaLN modulation vectors
    ada_kernel<<<dim3(D6 / 256, BB), 256>>>(c, W_ada,   b_ada,   ada);
    ada_kernel<<<dim3(D6 / 256, BB), 256>>>(c, W_ada_c, b_ada_c, ada_c);

    // 2) LN + modulate (MSA): offsets sh=0, sc=D
    ln_mod_kernel<<<M,  256>>>(x,    ada,   xt, NN,  0, DD);
    ln_mod_kernel<<<Mc, 256>>>(cond, ada_c, ct, NCC, 0, DD);

    // 3) QKV projections
    gemm_kernel<0><<<dim3(3 * DD / 128, M / 128),          256>>>(xt, W_qkv,   b_qkv,   nullptr, nullptr, 0, qkv,   M,  DD, 3 * DD, NN);
    gemm_kernel<0><<<dim3(3 * DD / 128, (Mc + 127) / 128), 256>>>(ct, W_qkv_c, b_qkv_c, nullptr, nullptr, 0, qkv_c, Mc, DD, 3 * DD, NCC);

    // 4) joint attention over [x tokens ++ cond tokens]
    attn_kernel<<<dim3((STOT + QT - 1) / QT, HH, BB), 256>>>(qkv, qkv_c, ax, acnd);

    // 5) output proj + gated residual (g_msa at offset 2D)
    gemm_kernel<2><<<dim3(DD / 128, M / 128),          256>>>(ax,   W_proj,   b_proj,   x,    ada,   2 * DD, x1, M,  DD, DD, NN);
    gemm_kernel<2><<<dim3(DD / 128, (Mc + 127) / 128), 256>>>(acnd, W_proj_c, b_proj_c, cond, ada_c, 2 * DD, c1, Mc, DD, DD, NCC);

    // 6) LN + modulate (MLP): offsets sh=3D, sc=4D
    ln_mod_kernel<<<M,  256>>>(x1, ada,   xt, NN,  3 * DD, 4 * DD);
    ln_mod_kernel<<<Mc, 256>>>(c1, ada_c, ct, NCC, 3 * DD, 4 * DD);

    // 7) fc1 + GELU
    gemm_kernel<1><<<dim3(DFF_ / 128, M / 128),          256>>>(xt, W_fc1,   b_fc1,   nullptr, nullptr, 0, hb,  M,  DD, DFF_, NN);
    gemm_kernel<1><<<dim3(DFF_ / 128, (Mc + 127) / 128), 256>>>(ct, W_fc1_c, b_fc1_c, nullptr, nullptr, 0, hbc, Mc, DD, DFF_, NCC);

    // 8) fc2 + gated residual (g_mlp at offset 5D) -> final outputs
    gemm_kernel<2><<<dim3(DD / 128, M / 128),          256>>>(hb,  W_fc2,   b_fc2,   x1, ada,   5 * DD, out_x, M,  DFF_, DD, NN);
    gemm_kernel<2><<<dim3(DD / 128, (Mc + 127) / 128), 256>>>(hbc, W_fc2_c, b_fc2_c, c1, ada_c, 5 * DD, out_c, Mc, DFF_, DD, NCC);
}

// round 7
// speedup vs baseline: 1.9669x; 1.9669x over previous
#include <cuda_runtime.h>
#include <cuda_bf16.h>
#include <math.h>
#include <stdint.h>

// Problem constants
#define BB   4
#define NN   1024
#define NCC  77
#define DD   1024
#define HH   16
#define HDD  64
#define DFF_ 4096
#define STOT (NN + NCC)   // 1101
#define D6   (6 * DD)

__device__ __forceinline__ uint32_t smem_to_u32(const void* p) {
    uint32_t a;
    asm("{ .reg .u64 t; cvta.to.shared.u64 t, %1; cvt.u32.u64 %0, t; }" : "=r"(a) : "l"(p));
    return a;
}

#define SMEM_SWZ(off) ((off) ^ (((off) >> 3) & 0x70))

// ---- base-target (sm_80+) tensor-core primitives: legal on compute_103 ----
__device__ __forceinline__ void ldsm4(uint32_t* r, uint32_t a) {
    asm volatile("ldmatrix.sync.aligned.m8n8.x4.shared.b16 {%0,%1,%2,%3}, [%4];"
                 : "=r"(r[0]), "=r"(r[1]), "=r"(r[2]), "=r"(r[3]) : "r"(a));
}
__device__ __forceinline__ void mma16816(float* d, const uint32_t* a, const uint32_t* b) {
    asm volatile("mma.sync.aligned.m16n8k16.row.col.f32.bf16.bf16.f32 "
                 "{%0,%1,%2,%3},{%4,%5,%6,%7},{%8,%9},{%0,%1,%2,%3};"
                 : "+f"(d[0]), "+f"(d[1]), "+f"(d[2]), "+f"(d[3])
                 : "r"(a[0]), "r"(a[1]), "r"(a[2]), "r"(a[3]), "r"(b[0]), "r"(b[1]));
}
#define CP_ASYNC16(dst, src) \
    asm volatile("cp.async.cg.shared.global [%0], [%1], 16;" :: "r"(dst), "l"(src))
#define CP_COMMIT() asm volatile("cp.async.commit_group;" ::: "memory")
#define CP_WAIT0()  asm volatile("cp.async.wait_group 0;" ::: "memory")

// ---------------------------------------------------------------------------
// Scratch (device globals — no allocations allowed)
// ---------------------------------------------------------------------------
__device__ float g_ada  [BB * D6];
__device__ float g_ada_c[BB * D6];
__device__ float g_xt   [BB * NN  * DD];
__device__ float g_ct   [BB * NCC * DD];
__device__ float g_qkv  [BB * NN  * 3 * DD];
__device__ float g_qkv_c[BB * NCC * 3 * DD];
__device__ float g_ax   [BB * NN  * DD];
__device__ float g_acnd [BB * NCC * DD];
__device__ float g_x1   [BB * NN  * DD];
__device__ float g_c1   [BB * NCC * DD];
__device__ float g_h    [BB * NN  * DFF_];
__device__ float g_hc   [BB * NCC * DFF_];

// bf16 split weights, transposed to [N][K]
__device__ __nv_bfloat16 g_wqkv_h [3 * DD * DD], g_wqkv_l [3 * DD * DD];
__device__ __nv_bfloat16 g_wqkvc_h[3 * DD * DD], g_wqkvc_l[3 * DD * DD];
__device__ __nv_bfloat16 g_wproj_h[DD * DD],     g_wproj_l[DD * DD];
__device__ __nv_bfloat16 g_wprojc_h[DD * DD],    g_wprojc_l[DD * DD];
__device__ __nv_bfloat16 g_wfc1_h [DD * DFF_],   g_wfc1_l [DD * DFF_];
__device__ __nv_bfloat16 g_wfc1c_h[DD * DFF_],   g_wfc1c_l[DD * DFF_];
__device__ __nv_bfloat16 g_wfc2_h [DFF_ * DD],   g_wfc2_l [DFF_ * DD];
__device__ __nv_bfloat16 g_wfc2c_h[DFF_ * DD],   g_wfc2c_l[DFF_ * DD];

// ---------------------------------------------------------------------------
// Weight convert+transpose: W[K][N] f32 -> Wt_hi/lo [N][K] bf16
// ---------------------------------------------------------------------------
__global__ void wconv_kernel(const float* __restrict__ W, __nv_bfloat16* __restrict__ hi,
                             __nv_bfloat16* __restrict__ lo, int K, int N)
{
    __shared__ float t[32][33];
    int k0 = blockIdx.y * 32, n0 = blockIdx.x * 32;
    int tx = threadIdx.x, ty = threadIdx.y;
#pragma unroll
    for (int i = 0; i < 32; i += 8)
        t[ty + i][tx] = W[(size_t)(k0 + ty + i) * N + n0 + tx];
    __syncthreads();
#pragma unroll
    for (int i = 0; i < 32; i += 8) {
        float v = t[tx][ty + i];
        int n = n0 + ty + i, k = k0 + tx;
        __nv_bfloat16 h = __float2bfloat16(v);
        hi[(size_t)n * K + k] = h;
        lo[(size_t)n * K + k] = __float2bfloat16(v - __bfloat162float(h));
    }
}

// ---------------------------------------------------------------------------
// adaLN: out[b,:] = silu(c[b,:]) @ W + bias
// ---------------------------------------------------------------------------
__global__ void ada_kernel(const float* __restrict__ c, const float* __restrict__ W,
                           const float* __restrict__ bias, float* __restrict__ out)
{
    int b = blockIdx.y;
    int j = blockIdx.x * 256 + threadIdx.x;
    __shared__ float sc[DD];
    for (int k = threadIdx.x; k < DD; k += 256) {
        float v = c[b * DD + k];
        sc[k] = v / (1.0f + expf(-v));
    }
    __syncthreads();
    float acc = bias[j];
#pragma unroll 8
    for (int k = 0; k < DD; k++)
        acc += sc[k] * W[(size_t)k * D6 + j];
    out[b * D6 + j] = acc;
}

// ---------------------------------------------------------------------------
// LayerNorm + modulate
// ---------------------------------------------------------------------------
__global__ void ln_mod_kernel(const float* __restrict__ x, const float* __restrict__ ada,
                              float* __restrict__ out, int tokens, int sh_off, int sc_off)
{
    int row = blockIdx.x;
    int b = row / tokens;
    const float* xr = x + (size_t)row * DD;
    float v[4];
    float s = 0.f, s2 = 0.f;
#pragma unroll
    for (int i = 0; i < 4; i++) {
        v[i] = xr[threadIdx.x + i * 256];
        s += v[i]; s2 += v[i] * v[i];
    }
#pragma unroll
    for (int o = 16; o; o >>= 1) {
        s  += __shfl_xor_sync(0xffffffffu, s, o);
        s2 += __shfl_xor_sync(0xffffffffu, s2, o);
    }
    __shared__ float ss[8], ss2[8];
    int w = threadIdx.x >> 5, ln = threadIdx.x & 31;
    if (ln == 0) { ss[w] = s; ss2[w] = s2; }
    __syncthreads();
    float S = 0.f, S2 = 0.f;
#pragma unroll
    for (int i = 0; i < 8; i++) { S += ss[i]; S2 += ss2[i]; }
    float mu  = S * (1.0f / DD);
    float var = S2 * (1.0f / DD) - mu * mu;
    float inv = rsqrtf(var + 1e-6f);
    const float* adab = ada + (size_t)b * D6;
#pragma unroll
    for (int i = 0; i < 4; i++) {
        int j = threadIdx.x + i * 256;
        out[(size_t)row * DD + j] = (v[i] - mu) * inv * (1.0f + adab[sc_off + j]) + adab[sh_off + j];
    }
}

// ---------------------------------------------------------------------------
// mma.sync bf16x3 GEMM: C[M,Nn] = A[M,K](f32) @ W[K,Nn] + bias.
//   MODE 0: bias; MODE 1: gelu; MODE 2: res + gate*(.)
// CTA 128x128, BK=64 chunks, double-buffered smem (SW128 rows of 128B),
// 256 threads = 8 warps (4x2), warp tile 32x64 = 2x8 m16n8k16 tiles.
// A: f32 gmem -> regs -> hi/lo bf16 smem.  B: pre-split bf16 [Nn][K], cp.async.
// Stage layout: Ahi@0, Alo@16384, Bhi@32768, Blo@49152 (16KB each).
// ---------------------------------------------------------------------------
#define GST 65536
#define GSM_TOTAL (2 * GST)

__device__ __forceinline__ uint32_t pack_bf2(__nv_bfloat16 a, __nv_bfloat16 b) {
    __nv_bfloat162 t = __halves2bfloat162(a, b);
    return *reinterpret_cast<uint32_t*>(&t);
}

template <int MODE>
__global__ void __launch_bounds__(256, 1)
mma_gemm(const float* __restrict__ A,
         const __nv_bfloat16* __restrict__ Bhi, const __nv_bfloat16* __restrict__ Blo,
         const float* __restrict__ bias, const float* __restrict__ res,
         const float* __restrict__ ada, int gate_off,
         float* __restrict__ C, int M, int K, int Nn, int tokens)
{
    extern __shared__ __align__(1024) char smem[];
    uint32_t sb = smem_to_u32(smem);
    int tid = threadIdx.x, wid = tid >> 5, lane = tid & 31;
    int bm = blockIdx.y * 128, bn = blockIdx.x * 128;
    int wm = (wid & 3) * 32;    // warp M offset in tile
    int wn = (wid >> 2) * 64;   // warp N offset in tile

    float acc[2][8][4];
#pragma unroll
    for (int i = 0; i < 2; i++)
#pragma unroll
        for (int j = 0; j < 8; j++)
#pragma unroll
            for (int k = 0; k < 4; k++) acc[i][j][k] = 0.f;

    const int NCHUNK = K >> 6;
    float4 areg[8];

    auto ldgA = [&](int k0) {
#pragma unroll
        for (int it = 0; it < 8; it++) {
            int idx = tid + it * 256;
            int row = idx >> 4, kq = idx & 15;
            if (bm + row < M) areg[it] = *(const float4*)(A + (size_t)(bm + row) * K + k0 + kq * 4);
            else              areg[it] = make_float4(0.f, 0.f, 0.f, 0.f);
        }
    };
    auto stsA = [&](int st) {
        char* base = smem + st * GST;
#pragma unroll
        for (int it = 0; it < 8; it++) {
            int idx = tid + it * 256;
            int row = idx >> 4, kq = idx & 15;
            float4 v = areg[it];
            __nv_bfloat16 h0 = __float2bfloat16(v.x), h1 = __float2bfloat16(v.y);
            __nv_bfloat16 h2 = __float2bfloat16(v.z), h3 = __float2bfloat16(v.w);
            __nv_bfloat16 l0 = __float2bfloat16(v.x - __bfloat162float(h0));
            __nv_bfloat16 l1 = __float2bfloat16(v.y - __bfloat162float(h1));
            __nv_bfloat16 l2 = __float2bfloat16(v.z - __bfloat162float(h2));
            __nv_bfloat16 l3 = __float2bfloat16(v.w - __bfloat162float(h3));
            uint32_t sw = SMEM_SWZ((uint32_t)(row * 128 + kq * 8));
            *(uint2*)(base + sw)         = make_uint2(pack_bf2(h0, h1), pack_bf2(h2, h3));
            *(uint2*)(base + 16384 + sw) = make_uint2(pack_bf2(l0, l1), pack_bf2(l2, l3));
        }
    };
    auto cpB = [&](int st, int k0) {
        uint32_t base = sb + st * GST;
#pragma unroll
        for (int it = 0; it < 4; it++) {
            int idx = tid + it * 256;
            int row = idx >> 3, kq = idx & 7;           // Nn multiple of 128: no guard
            uint32_t sw = SMEM_SWZ((uint32_t)(row * 128 + kq * 16));
            const __nv_bfloat16* gh = Bhi + (size_t)(bn + row) * K + k0 + kq * 8;
            const __nv_bfloat16* gl = Blo + (size_t)(bn + row) * K + k0 + kq * 8;
            CP_ASYNC16(base + 32768 + sw, gh);
            CP_ASYNC16(base + 49152 + sw, gl);
        }
        CP_COMMIT();
    };

    // frag addressing (SW128-swizzled)
    auto aaddr = [&](uint32_t abase, int mt, int ks) {
        int row = wm + mt * 16 + (lane & 15);
        uint32_t off = (uint32_t)(row * 128 + ks * 32 + ((lane >> 4) << 4));
        return abase + SMEM_SWZ(off);
    };
    auto baddr = [&](uint32_t bbase, int p, int ks) {
        int sub = lane >> 3;                           // 0..3
        int n = wn + p * 16 + (lane & 7) + ((sub >> 1) << 3);
        uint32_t off = (uint32_t)(n * 128 + ks * 32 + ((sub & 1) << 4));
        return bbase + SMEM_SWZ(off);
    };

    auto compute = [&](int st) {
        uint32_t aHi = sb + st * GST, aLo = aHi + 16384;
        uint32_t bHi = aHi + 32768,   bLo = aHi + 49152;
#pragma unroll
        for (int ks = 0; ks < 4; ks++) {
            uint32_t afr[2][4], bfr[8][2];
            // product 1: Ahi * Bhi
#pragma unroll
            for (int mt = 0; mt < 2; mt++) ldsm4(afr[mt], aaddr(aHi, mt, ks));
#pragma unroll
            for (int p = 0; p < 4; p++) {
                uint32_t t[4]; ldsm4(t, baddr(bHi, p, ks));
                bfr[2*p][0] = t[0]; bfr[2*p][1] = t[1];
                bfr[2*p+1][0] = t[2]; bfr[2*p+1][1] = t[3];
            }
#pragma unroll
            for (int mt = 0; mt < 2; mt++)
#pragma unroll
                for (int nt = 0; nt < 8; nt++) mma16816(acc[mt][nt], afr[mt], bfr[nt]);
            // product 2: Alo * Bhi (reuse Bhi frags)
#pragma unroll
            for (int mt = 0; mt < 2; mt++) ldsm4(afr[mt], aaddr(aLo, mt, ks));
#pragma unroll
            for (int mt = 0; mt < 2; mt++)
#pragma unroll
                for (int nt = 0; nt < 8; nt++) mma16816(acc[mt][nt], afr[mt], bfr[nt]);
            // product 3: Ahi * Blo (reload Ahi, load Blo)
#pragma unroll
            for (int mt = 0; mt < 2; mt++) ldsm4(afr[mt], aaddr(aHi, mt, ks));
#pragma unroll
            for (int p = 0; p < 4; p++) {
                uint32_t t[4]; ldsm4(t, baddr(bLo, p, ks));
                bfr[2*p][0] = t[0]; bfr[2*p][1] = t[1];
                bfr[2*p+1][0] = t[2]; bfr[2*p+1][1] = t[3];
            }
#pragma unroll
            for (int mt = 0; mt < 2; mt++)
#pragma unroll
                for (int nt = 0; nt < 8; nt++) mma16816(acc[mt][nt], afr[mt], bfr[nt]);
        }
    };

    // prologue: fill stage 0
    ldgA(0);
    cpB(0, 0);
    stsA(0);
    CP_WAIT0();
    __syncthreads();

    for (int i = 0; i < NCHUNK; i++) {
        int st = i & 1, nst = st ^ 1;
        bool more = (i + 1 < NCHUNK);
        if (more) { cpB(nst, (i + 1) * 64); ldgA((i + 1) * 64); }
        compute(st);
        if (more) { stsA(nst); CP_WAIT0(); }
        __syncthreads();
    }

    // epilogue: acc -> gmem with per-mode math
    int r0 = bm + wm + (lane >> 2);
    int c0 = bn + wn + (lane & 3) * 2;
#pragma unroll
    for (int mt = 0; mt < 2; mt++) {
#pragma unroll
        for (int h = 0; h < 2; h++) {
            int row = r0 + mt * 16 + h * 8;
            if (row >= M) continue;
            int b = row / tokens;
            size_t rb = (size_t)row * Nn;
#pragma unroll
            for (int nt = 0; nt < 8; nt++) {
                int col = c0 + nt * 8;
                float v0 = acc[mt][nt][h * 2 + 0] + bias[col];
                float v1 = acc[mt][nt][h * 2 + 1] + bias[col + 1];
                if (MODE == 1) {
                    float t0 = 0.7978845608028654f * (v0 + 0.044715f * v0 * v0 * v0);
                    float t1 = 0.7978845608028654f * (v1 + 0.044715f * v1 * v1 * v1);
                    v0 = 0.5f * v0 * (1.0f + tanhf(t0));
                    v1 = 0.5f * v1 * (1.0f + tanhf(t1));
                } else if (MODE == 2) {
                    const float* adab = ada + (size_t)b * D6 + gate_off;
                    v0 = res[rb + col]     + adab[col]     * v0;
                    v1 = res[rb + col + 1] + adab[col + 1] * v1;
                }
                float2 o; o.x = v0; o.y = v1;
                *(float2*)(C + rb + col) = o;
            }
        }
    }
}

// ---------------------------------------------------------------------------
// Attention (fp32 SIMT): QT=16 queries/block, 512 threads, 1 warp/query.
// ---------------------------------------------------------------------------
#define QT 16
#define CK 64
#define ATH 512

__global__ void __launch_bounds__(ATH)
attn_kernel(const float* __restrict__ qkv, const float* __restrict__ qkv_c,
            float* __restrict__ out_x, float* __restrict__ out_c)
{
    int b = blockIdx.z, h = blockIdx.y;
    int q0 = blockIdx.x * QT;
    int tid = threadIdx.x;
    int warp = tid >> 5, lane = tid & 31;

    __shared__ float q_s[QT][HDD];
    __shared__ float k_s[HDD][CK + 1];
    __shared__ float v_s[CK][HDD];
    __shared__ float p_s[QT][CK];

    for (int idx = tid; idx < QT * HDD; idx += ATH) {
        int qi = idx / HDD, d = idx % HDD;
        int s = q0 + qi;
        float val = 0.f;
        if (s < STOT) {
            if (s < NN) val = qkv[((size_t)(b * NN + s)) * 3072 + h * 64 + d];
            else        val = qkv_c[((size_t)(b * NCC + (s - NN))) * 3072 + h * 64 + d];
        }
        q_s[qi][d] = val * 0.125f;
    }
    __syncthreads();

    float m = -INFINITY, l = 0.f;
    float o0 = 0.f, o1 = 0.f;
    int myq = q0 + warp;

    for (int kc = 0; kc < STOT; kc += CK) {
        for (int idx = tid; idx < CK * HDD; idx += ATH) {
            int kk = idx / HDD, d = idx % HDD;
            int s = kc + kk;
            float kv = 0.f, vv = 0.f;
            if (s < STOT) {
                const float* src; size_t base;
                if (s < NN) { src = qkv;   base = ((size_t)(b * NN + s)) * 3072; }
                else        { src = qkv_c; base = ((size_t)(b * NCC + (s - NN))) * 3072; }
                kv = src[base + 1024 + h * 64 + d];
                vv = src[base + 2048 + h * 64 + d];
            }
            k_s[d][kk] = kv;
            v_s[kk][d] = vv;
        }
        __syncthreads();

        int nk = STOT - kc; if (nk > CK) nk = CK;
        float s0 = 0.f, s1 = 0.f;
#pragma unroll 8
        for (int d = 0; d < HDD; d++) {
            float qv = q_s[warp][d];
            s0 += qv * k_s[d][lane];
            s1 += qv * k_s[d][lane + 32];
        }
        if (lane      >= nk) s0 = -INFINITY;
        if (lane + 32 >= nk) s1 = -INFINITY;

        float mloc = fmaxf(s0, s1);
#pragma unroll
        for (int o = 16; o; o >>= 1) mloc = fmaxf(mloc, __shfl_xor_sync(0xffffffffu, mloc, o));
        float mnew = fmaxf(m, mloc);
        float corr = __expf(m - mnew);
        float p0 = __expf(s0 - mnew);
        float p1 = __expf(s1 - mnew);
        float psum = p0 + p1;
#pragma unroll
        for (int o = 16; o; o >>= 1) psum += __shfl_xor_sync(0xffffffffu, psum, o);
        l = l * corr + psum;
        o0 *= corr; o1 *= corr;
        m = mnew;

        p_s[warp][lane] = p0;
        p_s[warp][lane + 32] = p1;
        __syncwarp();
#pragma unroll 4
        for (int k2 = 0; k2 < CK; k2++) {
            float p = p_s[warp][k2];
            o0 += p * v_s[k2][lane];
            o1 += p * v_s[k2][lane + 32];
        }
        __syncthreads();
    }

    if (myq < STOT) {
        float invl = 1.0f / l;
        o0 *= invl; o1 *= invl;
        if (myq < NN) {
            float* o = out_x + ((size_t)(b * NN + myq)) * DD + h * 64;
            o[lane] = o0; o[lane + 32] = o1;
        } else {
            float* o = out_c + ((size_t)(b * NCC + (myq - NN))) * DD + h * 64;
            o[lane] = o0; o[lane + 32] = o1;
        }
    }
}

// ---------------------------------------------------------------------------
// Launch orchestration
// ---------------------------------------------------------------------------
extern "C" void kernel_launch(void* const* d_in, const int* in_sizes, int n_in,
                              void* d_out, int out_size)
{
    const float* x       = (const float*)d_in[0];
    const float* cond    = (const float*)d_in[1];
    const float* c       = (const float*)d_in[2];
    const float* W_ada   = (const float*)d_in[3];
    const float* b_ada   = (const float*)d_in[4];
    const float* W_ada_c = (const float*)d_in[5];
    const float* b_ada_c = (const float*)d_in[6];
    const float* W_qkv   = (const float*)d_in[7];
    const float* b_qkv   = (const float*)d_in[8];
    const float* W_proj  = (const float*)d_in[9];
    const float* b_proj  = (const float*)d_in[10];
    const float* W_qkv_c = (const float*)d_in[11];
    const float* b_qkv_c = (const float*)d_in[12];
    const float* W_proj_c= (const float*)d_in[13];
    const float* b_proj_c= (const float*)d_in[14];
    const float* W_fc1   = (const float*)d_in[15];
    const float* b_fc1   = (const float*)d_in[16];
    const float* W_fc2   = (const float*)d_in[17];
    const float* b_fc2   = (const float*)d_in[18];
    const float* W_fc1_c = (const float*)d_in[19];
    const float* b_fc1_c = (const float*)d_in[20];
    const float* W_fc2_c = (const float*)d_in[21];
    const float* b_fc2_c = (const float*)d_in[22];

    float* out   = (float*)d_out;
    float* out_x = out;
    float* out_c = out + (size_t)BB * NN * DD;

    float *ada, *ada_c, *xt, *ct, *qkv, *qkv_c, *ax, *acnd, *x1, *c1, *hb, *hbc;
    cudaGetSymbolAddress((void**)&ada,   g_ada);
    cudaGetSymbolAddress((void**)&ada_c, g_ada_c);
    cudaGetSymbolAddress((void**)&xt,    g_xt);
    cudaGetSymbolAddress((void**)&ct,    g_ct);
    cudaGetSymbolAddress((void**)&qkv,   g_qkv);
    cudaGetSymbolAddress((void**)&qkv_c, g_qkv_c);
    cudaGetSymbolAddress((void**)&ax,    g_ax);
    cudaGetSymbolAddress((void**)&acnd,  g_acnd);
    cudaGetSymbolAddress((void**)&x1,    g_x1);
    cudaGetSymbolAddress((void**)&c1,    g_c1);
    cudaGetSymbolAddress((void**)&hb,    g_h);
    cudaGetSymbolAddress((void**)&hbc,   g_hc);

    __nv_bfloat16 *wq_h, *wq_l, *wqc_h, *wqc_l, *wp_h, *wp_l, *wpc_h, *wpc_l;
    __nv_bfloat16 *w1_h, *w1_l, *w1c_h, *w1c_l, *w2_h, *w2_l, *w2c_h, *w2c_l;
    cudaGetSymbolAddress((void**)&wq_h,  g_wqkv_h);  cudaGetSymbolAddress((void**)&wq_l,  g_wqkv_l);
    cudaGetSymbolAddress((void**)&wqc_h, g_wqkvc_h); cudaGetSymbolAddress((void**)&wqc_l, g_wqkvc_l);
    cudaGetSymbolAddress((void**)&wp_h,  g_wproj_h); cudaGetSymbolAddress((void**)&wp_l,  g_wproj_l);
    cudaGetSymbolAddress((void**)&wpc_h, g_wprojc_h);cudaGetSymbolAddress((void**)&wpc_l, g_wprojc_l);
    cudaGetSymbolAddress((void**)&w1_h,  g_wfc1_h);  cudaGetSymbolAddress((void**)&w1_l,  g_wfc1_l);
    cudaGetSymbolAddress((void**)&w1c_h, g_wfc1c_h); cudaGetSymbolAddress((void**)&w1c_l, g_wfc1c_l);
    cudaGetSymbolAddress((void**)&w2_h,  g_wfc2_h);  cudaGetSymbolAddress((void**)&w2_l,  g_wfc2_l);
    cudaGetSymbolAddress((void**)&w2c_h, g_wfc2c_h); cudaGetSymbolAddress((void**)&w2c_l, g_wfc2c_l);

    // idempotent, every call (no static guards allowed)
    cudaFuncSetAttribute(mma_gemm<0>, cudaFuncAttributeMaxDynamicSharedMemorySize, GSM_TOTAL);
    cudaFuncSetAttribute(mma_gemm<1>, cudaFuncAttributeMaxDynamicSharedMemorySize, GSM_TOTAL);
    cudaFuncSetAttribute(mma_gemm<2>, cudaFuncAttributeMaxDynamicSharedMemorySize, GSM_TOTAL);

    const int M  = BB * NN;    // 4096
    const int Mc = BB * NCC;   // 308
    dim3 wb(32, 8);

    // 0) weight split + transpose (bf16 hi/lo, [N][K])
    wconv_kernel<<<dim3(3 * DD / 32, DD / 32),   wb>>>(W_qkv,    wq_h,  wq_l,  DD,   3 * DD);
    wconv_kernel<<<dim3(3 * DD / 32, DD / 32),   wb>>>(W_qkv_c,  wqc_h, wqc_l, DD,   3 * DD);
    wconv_kernel<<<dim3(DD / 32, DD / 32),       wb>>>(W_proj,   wp_h,  wp_l,  DD,   DD);
    wconv_kernel<<<dim3(DD / 32, DD / 32),       wb>>>(W_proj_c, wpc_h, wpc_l, DD,   DD);
    wconv_kernel<<<dim3(DFF_ / 32, DD / 32),     wb>>>(W_fc1,    w1_h,  w1_l,  DD,   DFF_);
    wconv_kernel<<<dim3(DFF_ / 32, DD / 32),     wb>>>(W_fc1_c,  w1c_h, w1c_l, DD,   DFF_);
    wconv_kernel<<<dim3(DD / 32, DFF_ / 32),     wb>>>(W_fc2,    w2_h,  w2_l,  DFF_, DD);
    wconv_kernel<<<dim3(DD / 32, DFF_ / 32),     wb>>>(W_fc2_c,  w2c_h, w2c_l, DFF_, DD);

    // 1) adaLN vectors
    ada_kernel<<<dim3(D6 / 256, BB), 256>>>(c, W_ada,   b_ada,   ada);
    ada_kernel<<<dim3(D6 / 256, BB), 256>>>(c, W_ada_c, b_ada_c, ada_c);

    // 2) LN + modulate (MSA)
    ln_mod_kernel<<<M,  256>>>(x,    ada,   xt, NN,  0, DD);
    ln_mod_kernel<<<Mc, 256>>>(cond, ada_c, ct, NCC, 0, DD);

    // 3) QKV
    mma_gemm<0><<<dim3(3 * DD / 128, M / 128),          256, GSM_TOTAL>>>(xt, wq_h,  wq_l,  b_qkv,   nullptr, nullptr, 0, qkv,   M,  DD, 3 * DD, NN);
    mma_gemm<0><<<dim3(3 * DD / 128, (Mc + 127) / 128), 256, GSM_TOTAL>>>(ct, wqc_h, wqc_l, b_qkv_c, nullptr, nullptr, 0, qkv_c, Mc, DD, 3 * DD, NCC);

    // 4) attention (QT=16, 512 threads)
    attn_kernel<<<dim3((STOT + QT - 1) / QT, HH, BB), ATH>>>(qkv, qkv_c, ax, acnd);

    // 5) proj + gated residual (g_msa @ 2D)
    mma_gemm<2><<<dim3(DD / 128, M / 128),          256, GSM_TOTAL>>>(ax,   wp_h,  wp_l,  b_proj,   x,    ada,   2 * DD, x1, M,  DD, DD, NN);
    mma_gemm<2><<<dim3(DD / 128, (Mc + 127) / 128), 256, GSM_TOTAL>>>(acnd, wpc_h, wpc_l, b_proj_c, cond, ada_c, 2 * DD, c1, Mc, DD, DD, NCC);

    // 6) LN + modulate (MLP)
    ln_mod_kernel<<<M,  256>>>(x1, ada,   xt, NN,  3 * DD, 4 * DD);
    ln_mod_kernel<<<Mc, 256>>>(c1, ada_c, ct, NCC, 3 * DD, 4 * DD);

    // 7) fc1 + GELU
    mma_gemm<1><<<dim3(DFF_ / 128, M / 128),          256, GSM_TOTAL>>>(xt, w1_h,  w1_l,  b_fc1,   nullptr, nullptr, 0, hb,  M,  DD, DFF_, NN);
    mma_gemm<1><<<dim3(DFF_ / 128, (Mc + 127) / 128), 256, GSM_TOTAL>>>(ct, w1c_h, w1c_l, b_fc1_c, nullptr, nullptr, 0, hbc, Mc, DD, DFF_, NCC);

    // 8) fc2 + gated residual (g_mlp @ 5D)
    mma_gemm<2><<<dim3(DD / 128, M / 128),          256, GSM_TOTAL>>>(hb,  w2_h,  w2_l,  b_fc2,   x1, ada,   5 * DD, out_x, M,  DFF_, DD, NN);
    mma_gemm<2><<<dim3(DD / 128, (Mc + 127) / 128), 256, GSM_TOTAL>>>(hbc, w2c_h, w2c_l, b_fc2_c, c1, ada_c, 5 * DD, out_c, Mc, DFF_, DD, NCC);
}

// round 12
// speedup vs baseline: 2.0166x; 1.0252x over previous
#include <cuda_runtime.h>
#include <cuda_bf16.h>
#include <math.h>
#include <stdint.h>

// Problem constants
#define BB   4
#define NN   1024
#define NCC  77
#define DD   1024
#define HH   16
#define HDD  64
#define DFF_ 4096
#define STOT (NN + NCC)   // 1101
#define D6   (6 * DD)

__device__ __forceinline__ uint32_t smem_to_u32(const void* p) {
    uint32_t a;
    asm("{ .reg .u64 t; cvta.to.shared.u64 t, %1; cvt.u32.u64 %0, t; }" : "=r"(a) : "l"(p));
    return a;
}

// 64B-row swizzle: toggles bits [5:4] with row bits — conflict-free ldsm on 64B rows
#define SMEM_SWZ32(off) ((off) ^ (((off) >> 3) & 0x30))

// ---- base-target (sm_80+) tensor-core primitives: legal on compute_103 ----
__device__ __forceinline__ void ldsm4(uint32_t* r, uint32_t a) {
    asm volatile("ldmatrix.sync.aligned.m8n8.x4.shared.b16 {%0,%1,%2,%3}, [%4];"
                 : "=r"(r[0]), "=r"(r[1]), "=r"(r[2]), "=r"(r[3]) : "r"(a));
}
__device__ __forceinline__ void mma16816(float* d, const uint32_t* a, const uint32_t* b) {
    asm volatile("mma.sync.aligned.m16n8k16.row.col.f32.bf16.bf16.f32 "
                 "{%0,%1,%2,%3},{%4,%5,%6,%7},{%8,%9},{%0,%1,%2,%3};"
                 : "+f"(d[0]), "+f"(d[1]), "+f"(d[2]), "+f"(d[3])
                 : "r"(a[0]), "r"(a[1]), "r"(a[2]), "r"(a[3]), "r"(b[0]), "r"(b[1]));
}
#define CP_ASYNC16(dst, src) \
    asm volatile("cp.async.cg.shared.global [%0], [%1], 16;" :: "r"(dst), "l"(src))
#define CP_ASYNC16Z(dst, src, n) \
    asm volatile("cp.async.cg.shared.global [%0], [%1], 16, %2;" :: "r"(dst), "l"(src), "r"(n))
#define CP_COMMIT() asm volatile("cp.async.commit_group;" ::: "memory")
#define CP_WAIT0()  asm volatile("cp.async.wait_group 0;" ::: "memory")
#define CP_WAIT1()  asm volatile("cp.async.wait_group 1;" ::: "memory")

__device__ __forceinline__ uint32_t pack_bf2(__nv_bfloat16 a, __nv_bfloat16 b) {
    __nv_bfloat162 t = __halves2bfloat162(a, b);
    return *reinterpret_cast<uint32_t*>(&t);
}

// ---------------------------------------------------------------------------
// Scratch (device globals — no allocations allowed)
// ---------------------------------------------------------------------------
__device__ float g_ada  [BB * D6];
__device__ float g_ada_c[BB * D6];
__device__ float g_qkv  [BB * NN  * 3 * DD];
__device__ float g_qkv_c[BB * NCC * 3 * DD];
__device__ float g_x1   [BB * NN  * DD];
__device__ float g_c1   [BB * NCC * DD];

// split-bf16 activations (producers write hi/lo pairs)
__device__ __nv_bfloat16 g_xt_h  [BB * NN  * DD],  g_xt_l  [BB * NN  * DD];
__device__ __nv_bfloat16 g_ct_h  [BB * NCC * DD],  g_ct_l  [BB * NCC * DD];
__device__ __nv_bfloat16 g_ax_h  [BB * NN  * DD],  g_ax_l  [BB * NN  * DD];
__device__ __nv_bfloat16 g_acnd_h[BB * NCC * DD],  g_acnd_l[BB * NCC * DD];
__device__ __nv_bfloat16 g_h_h   [BB * NN  * DFF_],g_h_l   [BB * NN  * DFF_];
__device__ __nv_bfloat16 g_hc_h  [BB * NCC * DFF_],g_hc_l  [BB * NCC * DFF_];

// bf16 split weights, transposed to [N][K]
__device__ __nv_bfloat16 g_wqkv_h [3 * DD * DD], g_wqkv_l [3 * DD * DD];
__device__ __nv_bfloat16 g_wqkvc_h[3 * DD * DD], g_wqkvc_l[3 * DD * DD];
__device__ __nv_bfloat16 g_wproj_h[DD * DD],     g_wproj_l[DD * DD];
__device__ __nv_bfloat16 g_wprojc_h[DD * DD],    g_wprojc_l[DD * DD];
__device__ __nv_bfloat16 g_wfc1_h [DD * DFF_],   g_wfc1_l [DD * DFF_];
__device__ __nv_bfloat16 g_wfc1c_h[DD * DFF_],   g_wfc1c_l[DD * DFF_];
__device__ __nv_bfloat16 g_wfc2_h [DFF_ * DD],   g_wfc2_l [DFF_ * DD];
__device__ __nv_bfloat16 g_wfc2c_h[DFF_ * DD],   g_wfc2c_l[DFF_ * DD];

// ---------------------------------------------------------------------------
// Weight convert+transpose: W[K][N] f32 -> Wt_hi/lo [N][K] bf16
// ---------------------------------------------------------------------------
__global__ void wconv_kernel(const float* __restrict__ W, __nv_bfloat16* __restrict__ hi,
                             __nv_bfloat16* __restrict__ lo, int K, int N)
{
    __shared__ float t[32][33];
    int k0 = blockIdx.y * 32, n0 = blockIdx.x * 32;
    int tx = threadIdx.x, ty = threadIdx.y;
#pragma unroll
    for (int i = 0; i < 32; i += 8)
        t[ty + i][tx] = W[(size_t)(k0 + ty + i) * N + n0 + tx];
    __syncthreads();
#pragma unroll
    for (int i = 0; i < 32; i += 8) {
        float v = t[tx][ty + i];
        int n = n0 + ty + i, k = k0 + tx;
        __nv_bfloat16 h = __float2bfloat16(v);
        hi[(size_t)n * K + k] = h;
        lo[(size_t)n * K + k] = __float2bfloat16(v - __bfloat162float(h));
    }
}

// ---------------------------------------------------------------------------
// adaLN: out[b,:] = silu(c[b,:]) @ W + bias
// ---------------------------------------------------------------------------
__global__ void ada_kernel(const float* __restrict__ c, const float* __restrict__ W,
                           const float* __restrict__ bias, float* __restrict__ out)
{
    int b = blockIdx.y;
    int j = blockIdx.x * 256 + threadIdx.x;
    __shared__ float sc[DD];
    for (int k = threadIdx.x; k < DD; k += 256) {
        float v = c[b * DD + k];
        sc[k] = v / (1.0f + expf(-v));
    }
    __syncthreads();
    float acc = bias[j];
#pragma unroll 8
    for (int k = 0; k < DD; k++)
        acc += sc[k] * W[(size_t)k * D6 + j];
    out[b * D6 + j] = acc;
}

// ---------------------------------------------------------------------------
// LayerNorm + modulate -> split bf16 hi/lo
// ---------------------------------------------------------------------------
__global__ void ln_mod_kernel(const float* __restrict__ x, const float* __restrict__ ada,
                              __nv_bfloat16* __restrict__ out_h, __nv_bfloat16* __restrict__ out_l,
                              int tokens, int sh_off, int sc_off)
{
    int row = blockIdx.x;
    int b = row / tokens;
    const float* xr = x + (size_t)row * DD;
    float v[4];
    float s = 0.f, s2 = 0.f;
#pragma unroll
    for (int i = 0; i < 4; i++) {
        v[i] = xr[threadIdx.x + i * 256];
        s += v[i]; s2 += v[i] * v[i];
    }
#pragma unroll
    for (int o = 16; o; o >>= 1) {
        s  += __shfl_xor_sync(0xffffffffu, s, o);
        s2 += __shfl_xor_sync(0xffffffffu, s2, o);
    }
    __shared__ float ss[8], ss2[8];
    int w = threadIdx.x >> 5, ln = threadIdx.x & 31;
    if (ln == 0) { ss[w] = s; ss2[w] = s2; }
    __syncthreads();
    float S = 0.f, S2 = 0.f;
#pragma unroll
    for (int i = 0; i < 8; i++) { S += ss[i]; S2 += ss2[i]; }
    float mu  = S * (1.0f / DD);
    float var = S2 * (1.0f / DD) - mu * mu;
    float inv = rsqrtf(var + 1e-6f);
    const float* adab = ada + (size_t)b * D6;
#pragma unroll
    for (int i = 0; i < 4; i++) {
        int j = threadIdx.x + i * 256;
        float r = (v[i] - mu) * inv * (1.0f + adab[sc_off + j]) + adab[sh_off + j];
        __nv_bfloat16 h = __float2bfloat16(r);
        out_h[(size_t)row * DD + j] = h;
        out_l[(size_t)row * DD + j] = __float2bfloat16(r - __bfloat162float(h));
    }
}

// ---------------------------------------------------------------------------
// mma.sync bf16x3 GEMM, all-cp.async pipeline:
//   C[M,Nn] = A[M,K] @ W[K,Nn] + bias   (A, W given as hi/lo bf16, [M][K] / [Nn][K])
//   MODE 0: fp32 out + bias; MODE 1: gelu -> bf16 hi/lo out; MODE 2: fp32 res + gate*(.)
// CTA 128x128, BK=32 chunks (64B rows, SWZ32), 3-stage cp.async ring (96KB),
// 256 threads = 8 warps (4x2), warp tile 32x64 = 2x8 m16n8k16 tiles, 2 CTAs/SM.
// Stage layout: Ahi@0, Alo@8192, Bhi@16384, Blo@24576 (8KB each, 32KB/stage).
// ---------------------------------------------------------------------------
#define GST 32768
#define GSM_TOTAL (3 * GST)

template <int MODE>
__global__ void __launch_bounds__(256, 2)
mma_gemm(const __nv_bfloat16* __restrict__ Ahi, const __nv_bfloat16* __restrict__ Alo,
         const __nv_bfloat16* __restrict__ Bhi, const __nv_bfloat16* __restrict__ Blo,
         const float* __restrict__ bias, const float* __restrict__ res,
         const float* __restrict__ ada, int gate_off,
         float* __restrict__ C, __nv_bfloat16* __restrict__ Ch, __nv_bfloat16* __restrict__ Cl,
         int M, int K, int Nn, int tokens)
{
    extern __shared__ __align__(1024) char smem[];
    uint32_t sb = smem_to_u32(smem);
    int tid = threadIdx.x, wid = tid >> 5, lane = tid & 31;
    int bm = blockIdx.y * 128, bn = blockIdx.x * 128;
    int wm = (wid & 3) * 32;
    int wn = (wid >> 2) * 64;

    float acc[2][8][4];
#pragma unroll
    for (int i = 0; i < 2; i++)
#pragma unroll
        for (int j = 0; j < 8; j++)
#pragma unroll
            for (int k = 0; k < 4; k++) acc[i][j][k] = 0.f;

    const int NCHUNK = K >> 5;

    auto cp_stage = [&](int st, int k0) {
        uint32_t base = sb + st * GST;
#pragma unroll
        for (int it = 0; it < 2; it++) {
            int idx = tid + it * 256;          // 0..511
            int row = idx >> 2, c = idx & 3;   // 128 rows x 4 x 16B
            uint32_t sw = SMEM_SWZ32((uint32_t)(row * 64 + c * 16));
            size_t arow = (bm + row < M) ? (size_t)(bm + row) : 0;
            int an = (bm + row < M) ? 16 : 0;
            CP_ASYNC16Z(base + sw,        Ahi + arow * K + k0 + c * 8, an);
            CP_ASYNC16Z(base + 8192 + sw, Alo + arow * K + k0 + c * 8, an);
            // Nn is a multiple of 128 -> B rows always valid
            CP_ASYNC16(base + 16384 + sw, Bhi + (size_t)(bn + row) * K + k0 + c * 8);
            CP_ASYNC16(base + 24576 + sw, Blo + (size_t)(bn + row) * K + k0 + c * 8);
        }
        CP_COMMIT();
    };

    auto aaddr = [&](uint32_t abase, int mt, int ks) {
        int row = wm + mt * 16 + (lane & 15);
        uint32_t off = (uint32_t)(row * 64 + ks * 32 + ((lane >> 4) << 4));
        return abase + SMEM_SWZ32(off);
    };
    auto baddr = [&](uint32_t bbase, int p, int ks) {
        int sub = lane >> 3;
        int n = wn + p * 16 + (lane & 7) + ((sub >> 1) << 3);
        uint32_t off = (uint32_t)(n * 64 + ks * 32 + ((sub & 1) << 4));
        return bbase + SMEM_SWZ32(off);
    };

    auto compute = [&](int st) {
        uint32_t aHi = sb + st * GST, aLo = aHi + 8192;
        uint32_t bHi = aHi + 16384,   bLo = aHi + 24576;
#pragma unroll
        for (int ks = 0; ks < 2; ks++) {
            uint32_t afr[2][4], bfr[8][2];
            // product 1: Ahi * Bhi
#pragma unroll
            for (int mt = 0; mt < 2; mt++) ldsm4(afr[mt], aaddr(aHi, mt, ks));
#pragma unroll
            for (int p = 0; p < 4; p++) {
                uint32_t t[4]; ldsm4(t, baddr(bHi, p, ks));
                bfr[2*p][0] = t[0]; bfr[2*p][1] = t[1];
                bfr[2*p+1][0] = t[2]; bfr[2*p+1][1] = t[3];
            }
#pragma unroll
            for (int mt = 0; mt < 2; mt++)
#pragma unroll
                for (int nt = 0; nt < 8; nt++) mma16816(acc[mt][nt], afr[mt], bfr[nt]);
            // product 2: Alo * Bhi (reuse Bhi frags)
#pragma unroll
            for (int mt = 0; mt < 2; mt++) ldsm4(afr[mt], aaddr(aLo, mt, ks));
#pragma unroll
            for (int mt = 0; mt < 2; mt++)
#pragma unroll
                for (int nt = 0; nt < 8; nt++) mma16816(acc[mt][nt], afr[mt], bfr[nt]);
            // product 3: Ahi * Blo
#pragma unroll
            for (int mt = 0; mt < 2; mt++) ldsm4(afr[mt], aaddr(aHi, mt, ks));
#pragma unroll
            for (int p = 0; p < 4; p++) {
                uint32_t t[4]; ldsm4(t, baddr(bLo, p, ks));
                bfr[2*p][0] = t[0]; bfr[2*p][1] = t[1];
                bfr[2*p+1][0] = t[2]; bfr[2*p+1][1] = t[3];
            }
#pragma unroll
            for (int mt = 0; mt < 2; mt++)
#pragma unroll
                for (int nt = 0; nt < 8; nt++) mma16816(acc[mt][nt], afr[mt], bfr[nt]);
        }
    };

    // prologue: 2 stages in flight
    cp_stage(0, 0);
    cp_stage(1, 32);

    for (int i = 0; i < NCHUNK; i++) {
        if (i + 2 < NCHUNK) { CP_WAIT1(); } else { CP_WAIT0(); }
        __syncthreads();
        if (i + 2 < NCHUNK) cp_stage((i + 2) % 3, (i + 2) * 32);
        compute(i % 3);
    }

    // epilogue
    int r0 = bm + wm + (lane >> 2);
    int c0 = bn + wn + (lane & 3) * 2;
#pragma unroll
    for (int mt = 0; mt < 2; mt++) {
#pragma unroll
        for (int h = 0; h < 2; h++) {
            int row = r0 + mt * 16 + h * 8;
            if (row >= M) continue;
            int b = row / tokens;
            size_t rb = (size_t)row * Nn;
#pragma unroll
            for (int nt = 0; nt < 8; nt++) {
                int col = c0 + nt * 8;
                float v0 = acc[mt][nt][h * 2 + 0] + bias[col];
                float v1 = acc[mt][nt][h * 2 + 1] + bias[col + 1];
                if (MODE == 1) {
                    float t0 = 0.7978845608028654f * (v0 + 0.044715f * v0 * v0 * v0);
                    float t1 = 0.7978845608028654f * (v1 + 0.044715f * v1 * v1 * v1);
                    v0 = 0.5f * v0 * (1.0f + tanhf(t0));
                    v1 = 0.5f * v1 * (1.0f + tanhf(t1));
                    __nv_bfloat16 h0 = __float2bfloat16(v0), h1 = __float2bfloat16(v1);
                    __nv_bfloat16 l0 = __float2bfloat16(v0 - __bfloat162float(h0));
                    __nv_bfloat16 l1 = __float2bfloat16(v1 - __bfloat162float(h1));
                    *(uint32_t*)(Ch + rb + col) = pack_bf2(h0, h1);
                    *(uint32_t*)(Cl + rb + col) = pack_bf2(l0, l1);
                } else {
                    if (MODE == 2) {
                        const float* adab = ada + (size_t)b * D6 + gate_off;
                        v0 = res[rb + col]     + adab[col]     * v0;
                        v1 = res[rb + col + 1] + adab[col + 1] * v1;
                    }
                    float2 o; o.x = v0; o.y = v1;
                    *(float2*)(C + rb + col) = o;
                }
            }
        }
    }
}

// ---------------------------------------------------------------------------
// Attention (fp32 SIMT): QT=16 queries/block, 512 threads, 1 warp/query.
// Output written as split bf16 hi/lo (exact split of fp32 result).
// ---------------------------------------------------------------------------
#define QT 16
#define CK 64
#define ATH 512

__global__ void __launch_bounds__(ATH)
attn_kernel(const float* __restrict__ qkv, const float* __restrict__ qkv_c,
            __nv_bfloat16* __restrict__ axh, __nv_bfloat16* __restrict__ axl,
            __nv_bfloat16* __restrict__ ach, __nv_bfloat16* __restrict__ acl)
{
    int b = blockIdx.z, h = blockIdx.y;
    int q0 = blockIdx.x * QT;
    int tid = threadIdx.x;
    int warp = tid >> 5, lane = tid & 31;

    __shared__ float q_s[QT][HDD];
    __shared__ float k_s[HDD][CK + 1];
    __shared__ float v_s[CK][HDD];
    __shared__ float p_s[QT][CK];

    for (int idx = tid; idx < QT * HDD; idx += ATH) {
        int qi = idx / HDD, d = idx % HDD;
        int s = q0 + qi;
        float val = 0.f;
        if (s < STOT) {
            if (s < NN) val = qkv[((size_t)(b * NN + s)) * 3072 + h * 64 + d];
            else        val = qkv_c[((size_t)(b * NCC + (s - NN))) * 3072 + h * 64 + d];
        }
        q_s[qi][d] = val * 0.125f;
    }
    __syncthreads();

    float m = -INFINITY, l = 0.f;
    float o0 = 0.f, o1 = 0.f;
    int myq = q0 + warp;

    for (int kc = 0; kc < STOT; kc += CK) {
        for (int idx = tid; idx < CK * HDD; idx += ATH) {
            int kk = idx / HDD, d = idx % HDD;
            int s = kc + kk;
            float kv = 0.f, vv = 0.f;
            if (s < STOT) {
                const float* src; size_t base;
                if (s < NN) { src = qkv;   base = ((size_t)(b * NN + s)) * 3072; }
                else        { src = qkv_c; base = ((size_t)(b * NCC + (s - NN))) * 3072; }
                kv = src[base + 1024 + h * 64 + d];
                vv = src[base + 2048 + h * 64 + d];
            }
            k_s[d][kk] = kv;
            v_s[kk][d] = vv;
        }
        __syncthreads();

        int nk = STOT - kc; if (nk > CK) nk = CK;
        float s0 = 0.f, s1 = 0.f;
#pragma unroll 8
        for (int d = 0; d < HDD; d++) {
            float qv = q_s[warp][d];
            s0 += qv * k_s[d][lane];
            s1 += qv * k_s[d][lane + 32];
        }
        if (lane      >= nk) s0 = -INFINITY;
        if (lane + 32 >= nk) s1 = -INFINITY;

        float mloc = fmaxf(s0, s1);
#pragma unroll
        for (int o = 16; o; o >>= 1) mloc = fmaxf(mloc, __shfl_xor_sync(0xffffffffu, mloc, o));
        float mnew = fmaxf(m, mloc);
        float corr = __expf(m - mnew);
        float p0 = __expf(s0 - mnew);
        float p1 = __expf(s1 - mnew);
        float psum = p0 + p1;
#pragma unroll
        for (int o = 16; o; o >>= 1) psum += __shfl_xor_sync(0xffffffffu, psum, o);
        l = l * corr + psum;
        o0 *= corr; o1 *= corr;
        m = mnew;

        p_s[warp][lane] = p0;
        p_s[warp][lane + 32] = p1;
        __syncwarp();
#pragma unroll 4
        for (int k2 = 0; k2 < CK; k2++) {
            float p = p_s[warp][k2];
            o0 += p * v_s[k2][lane];
            o1 += p * v_s[k2][lane + 32];
        }
        __syncthreads();
    }

    if (myq < STOT) {
        float invl = 1.0f / l;
        o0 *= invl; o1 *= invl;
        __nv_bfloat16 h0 = __float2bfloat16(o0), h1 = __float2bfloat16(o1);
        __nv_bfloat16 l0 = __float2bfloat16(o0 - __bfloat162float(h0));
        __nv_bfloat16 l1 = __float2bfloat16(o1 - __bfloat162float(h1));
        if (myq < NN) {
            size_t base = ((size_t)(b * NN + myq)) * DD + h * 64;
            axh[base + lane] = h0; axh[base + lane + 32] = h1;
            axl[base + lane] = l0; axl[base + lane + 32] = l1;
        } else {
            size_t base = ((size_t)(b * NCC + (myq - NN))) * DD + h * 64;
            ach[base + lane] = h0; ach[base + lane + 32] = h1;
            acl[base + lane] = l0; acl[base + lane + 32] = l1;
        }
    }
}

// ---------------------------------------------------------------------------
// Launch orchestration
// ---------------------------------------------------------------------------
extern "C" void kernel_launch(void* const* d_in, const int* in_sizes, int n_in,
                              void* d_out, int out_size)
{
    const float* x       = (const float*)d_in[0];
    const float* cond    = (const float*)d_in[1];
    const float* c       = (const float*)d_in[2];
    const float* W_ada   = (const float*)d_in[3];
    const float* b_ada   = (const float*)d_in[4];
    const float* W_ada_c = (const float*)d_in[5];
    const float* b_ada_c = (const float*)d_in[6];
    const float* W_qkv   = (const float*)d_in[7];
    const float* b_qkv   = (const float*)d_in[8];
    const float* W_proj  = (const float*)d_in[9];
    const float* b_proj  = (const float*)d_in[10];
    const float* W_qkv_c = (const float*)d_in[11];
    const float* b_qkv_c = (const float*)d_in[12];
    const float* W_proj_c= (const float*)d_in[13];
    const float* b_proj_c= (const float*)d_in[14];
    const float* W_fc1   = (const float*)d_in[15];
    const float* b_fc1   = (const float*)d_in[16];
    const float* W_fc2   = (const float*)d_in[17];
    const float* b_fc2   = (const float*)d_in[18];
    const float* W_fc1_c = (const float*)d_in[19];
    const float* b_fc1_c = (const float*)d_in[20];
    const float* W_fc2_c = (const float*)d_in[21];
    const float* b_fc2_c = (const float*)d_in[22];

    float* out   = (float*)d_out;
    float* out_x = out;
    float* out_c = out + (size_t)BB * NN * DD;

    float *ada, *ada_c, *qkv, *qkv_c, *x1, *c1;
    cudaGetSymbolAddress((void**)&ada,   g_ada);
    cudaGetSymbolAddress((void**)&ada_c, g_ada_c);
    cudaGetSymbolAddress((void**)&qkv,   g_qkv);
    cudaGetSymbolAddress((void**)&qkv_c, g_qkv_c);
    cudaGetSymbolAddress((void**)&x1,    g_x1);
    cudaGetSymbolAddress((void**)&c1,    g_c1);

    __nv_bfloat16 *xt_h, *xt_l, *ct_h, *ct_l, *ax_h, *ax_l, *ac_h, *ac_l, *h_h, *h_l, *hc_h, *hc_l;
    cudaGetSymbolAddress((void**)&xt_h, g_xt_h);   cudaGetSymbolAddress((void**)&xt_l, g_xt_l);
    cudaGetSymbolAddress((void**)&ct_h, g_ct_h);   cudaGetSymbolAddress((void**)&ct_l, g_ct_l);
    cudaGetSymbolAddress((void**)&ax_h, g_ax_h);   cudaGetSymbolAddress((void**)&ax_l, g_ax_l);
    cudaGetSymbolAddress((void**)&ac_h, g_acnd_h); cudaGetSymbolAddress((void**)&ac_l, g_acnd_l);
    cudaGetSymbolAddress((void**)&h_h,  g_h_h);    cudaGetSymbolAddress((void**)&h_l,  g_h_l);
    cudaGetSymbolAddress((void**)&hc_h, g_hc_h);   cudaGetSymbolAddress((void**)&hc_l, g_hc_l);

    __nv_bfloat16 *wq_h, *wq_l, *wqc_h, *wqc_l, *wp_h, *wp_l, *wpc_h, *wpc_l;
    __nv_bfloat16 *w1_h, *w1_l, *w1c_h, *w1c_l, *w2_h, *w2_l, *w2c_h, *w2c_l;
    cudaGetSymbolAddress((void**)&wq_h,  g_wqkv_h);  cudaGetSymbolAddress((void**)&wq_l,  g_wqkv_l);
    cudaGetSymbolAddress((void**)&wqc_h, g_wqkvc_h); cudaGetSymbolAddress((void**)&wqc_l, g_wqkvc_l);
    cudaGetSymbolAddress((void**)&wp_h,  g_wproj_h); cudaGetSymbolAddress((void**)&wp_l,  g_wproj_l);
    cudaGetSymbolAddress((void**)&wpc_h, g_wprojc_h);cudaGetSymbolAddress((void**)&wpc_l, g_wprojc_l);
    cudaGetSymbolAddress((void**)&w1_h,  g_wfc1_h);  cudaGetSymbolAddress((void**)&w1_l,  g_wfc1_l);
    cudaGetSymbolAddress((void**)&w1c_h, g_wfc1c_h); cudaGetSymbolAddress((void**)&w1c_l, g_wfc1c_l);
    cudaGetSymbolAddress((void**)&w2_h,  g_wfc2_h);  cudaGetSymbolAddress((void**)&w2_l,  g_wfc2_l);
    cudaGetSymbolAddress((void**)&w2c_h, g_wfc2c_h); cudaGetSymbolAddress((void**)&w2c_l, g_wfc2c_l);

    cudaFuncSetAttribute(mma_gemm<0>, cudaFuncAttributeMaxDynamicSharedMemorySize, GSM_TOTAL);
    cudaFuncSetAttribute(mma_gemm<1>, cudaFuncAttributeMaxDynamicSharedMemorySize, GSM_TOTAL);
    cudaFuncSetAttribute(mma_gemm<2>, cudaFuncAttributeMaxDynamicSharedMemorySize, GSM_TOTAL);

    const int M  = BB * NN;    // 4096
    const int Mc = BB * NCC;   // 308
    dim3 wb(32, 8);

    // 0) weight split + transpose (bf16 hi/lo, [N][K])
    wconv_kernel<<<dim3(3 * DD / 32, DD / 32),   wb>>>(W_qkv,    wq_h,  wq_l,  DD,   3 * DD);
    wconv_kernel<<<dim3(3 * DD / 32, DD / 32),   wb>>>(W_qkv_c,  wqc_h, wqc_l, DD,   3 * DD);
    wconv_kernel<<<dim3(DD / 32, DD / 32),       wb>>>(W_proj,   wp_h,  wp_l,  DD,   DD);
    wconv_kernel<<<dim3(DD / 32, DD / 32),       wb>>>(W_proj_c, wpc_h, wpc_l, DD,   DD);
    wconv_kernel<<<dim3(DFF_ / 32, DD / 32),     wb>>>(W_fc1,    w1_h,  w1_l,  DD,   DFF_);
    wconv_kernel<<<dim3(DFF_ / 32, DD / 32),     wb>>>(W_fc1_c,  w1c_h, w1c_l, DD,   DFF_);
    wconv_kernel<<<dim3(DD / 32, DFF_ / 32),     wb>>>(W_fc2,    w2_h,  w2_l,  DFF_, DD);
    wconv_kernel<<<dim3(DD / 32, DFF_ / 32),     wb>>>(W_fc2_c,  w2c_h, w2c_l, DFF_, DD);

    // 1) adaLN vectors
    ada_kernel<<<dim3(D6 / 256, BB), 256>>>(c, W_ada,   b_ada,   ada);
    ada_kernel<<<dim3(D6 / 256, BB), 256>>>(c, W_ada_c, b_ada_c, ada_c);

    // 2) LN + modulate (MSA) -> split bf16
    ln_mod_kernel<<<M,  256>>>(x,    ada,   xt_h, xt_l, NN,  0, DD);
    ln_mod_kernel<<<Mc, 256>>>(cond, ada_c, ct_h, ct_l, NCC, 0, DD);

    // 3) QKV (fp32 out)
    mma_gemm<0><<<dim3(3 * DD / 128, M / 128),          256, GSM_TOTAL>>>(xt_h, xt_l, wq_h,  wq_l,  b_qkv,   nullptr, nullptr, 0, qkv,   nullptr, nullptr, M,  DD, 3 * DD, NN);
    mma_gemm<0><<<dim3(3 * DD / 128, (Mc + 127) / 128), 256, GSM_TOTAL>>>(ct_h, ct_l, wqc_h, wqc_l, b_qkv_c, nullptr, nullptr, 0, qkv_c, nullptr, nullptr, Mc, DD, 3 * DD, NCC);

    // 4) attention -> split bf16
    attn_kernel<<<dim3((STOT + QT - 1) / QT, HH, BB), ATH>>>(qkv, qkv_c, ax_h, ax_l, ac_h, ac_l);

    // 5) proj + gated residual (g_msa @ 2D) -> fp32
    mma_gemm<2><<<dim3(DD / 128, M / 128),          256, GSM_TOTAL>>>(ax_h, ax_l, wp_h,  wp_l,  b_proj,   x,    ada,   2 * DD, x1, nullptr, nullptr, M,  DD, DD, NN);
    mma_gemm<2><<<dim3(DD / 128, (Mc + 127) / 128), 256, GSM_TOTAL>>>(ac_h, ac_l, wpc_h, wpc_l, b_proj_c, cond, ada_c, 2 * DD, c1, nullptr, nullptr, Mc, DD, DD, NCC);

    // 6) LN + modulate (MLP) -> split bf16
    ln_mod_kernel<<<M,  256>>>(x1, ada,   xt_h, xt_l, NN,  3 * DD, 4 * DD);
    ln_mod_kernel<<<Mc, 256>>>(c1, ada_c, ct_h, ct_l, NCC, 3 * DD, 4 * DD);

    // 7) fc1 + GELU -> split bf16
    mma_gemm<1><<<dim3(DFF_ / 128, M / 128),          256, GSM_TOTAL>>>(xt_h, xt_l, w1_h,  w1_l,  b_fc1,   nullptr, nullptr, 0, nullptr, h_h,  h_l,  M,  DD, DFF_, NN);
    mma_gemm<1><<<dim3(DFF_ / 128, (Mc + 127) / 128), 256, GSM_TOTAL>>>(ct_h, ct_l, w1c_h, w1c_l, b_fc1_c, nullptr, nullptr, 0, nullptr, hc_h, hc_l, Mc, DD, DFF_, NCC);

    // 8) fc2 + gated residual (g_mlp @ 5D) -> fp32 final outputs
    mma_gemm<2><<<dim3(DD / 128, M / 128),          256, GSM_TOTAL>>>(h_h,  h_l,  w2_h,  w2_l,  b_fc2,   x1, ada,   5 * DD, out_x, nullptr, nullptr, M,  DFF_, DD, NN);
    mma_gemm<2><<<dim3(DD / 128, (Mc + 127) / 128), 256, GSM_TOTAL>>>(hc_h, hc_l, w2c_h, w2c_l, b_fc2_c, c1, ada_c, 5 * DD, out_c, nullptr, nullptr, Mc, DFF_, DD, NCC);
}

// round 16
// speedup vs baseline: 2.3298x; 1.1553x over previous
#include <cuda_runtime.h>
#include <cuda_bf16.h>
#include <math.h>
#include <stdint.h>

// Problem constants
#define BB   4
#define NN   1024
#define NCC  77
#define DD   1024
#define HH   16
#define HDD  64
#define DFF_ 4096
#define STOT (NN + NCC)   // 1101
#define D6   (6 * DD)
#define MX   (BB * NN)    // 4096
#define MC   (BB * NCC)   // 308
#define MYC  3            // ceil(308/128)

__device__ __forceinline__ uint32_t smem_to_u32(const void* p) {
    uint32_t a;
    asm("{ .reg .u64 t; cvta.to.shared.u64 t, %1; cvt.u32.u64 %0, t; }" : "=r"(a) : "l"(p));
    return a;
}

// 64B-row swizzle: conflict-free ldsm on 64B rows
#define SMEM_SWZ32(off) ((off) ^ (((off) >> 3) & 0x30))

// ---- base-target (sm_80+) tensor-core primitives: legal on compute_103 ----
__device__ __forceinline__ void ldsm4(uint32_t* r, uint32_t a) {
    asm volatile("ldmatrix.sync.aligned.m8n8.x4.shared.b16 {%0,%1,%2,%3}, [%4];"
                 : "=r"(r[0]), "=r"(r[1]), "=r"(r[2]), "=r"(r[3]) : "r"(a));
}
__device__ __forceinline__ void mma16816(float* d, const uint32_t* a, const uint32_t* b) {
    asm volatile("mma.sync.aligned.m16n8k16.row.col.f32.bf16.bf16.f32 "
                 "{%0,%1,%2,%3},{%4,%5,%6,%7},{%8,%9},{%0,%1,%2,%3};"
                 : "+f"(d[0]), "+f"(d[1]), "+f"(d[2]), "+f"(d[3])
                 : "r"(a[0]), "r"(a[1]), "r"(a[2]), "r"(a[3]), "r"(b[0]), "r"(b[1]));
}
#define CP_ASYNC16(dst, src) \
    asm volatile("cp.async.cg.shared.global [%0], [%1], 16;" :: "r"(dst), "l"(src))
#define CP_ASYNC16Z(dst, src, n) \
    asm volatile("cp.async.cg.shared.global [%0], [%1], 16, %2;" :: "r"(dst), "l"(src), "r"(n))
#define CP_COMMIT() asm volatile("cp.async.commit_group;" ::: "memory")
#define CP_WAIT0()  asm volatile("cp.async.wait_group 0;" ::: "memory")
#define CP_WAIT1()  asm volatile("cp.async.wait_group 1;" ::: "memory")

__device__ __forceinline__ uint32_t pack_bf2(__nv_bfloat16 a, __nv_bfloat16 b) {
    __nv_bfloat162 t = __halves2bfloat162(a, b);
    return *reinterpret_cast<uint32_t*>(&t);
}

// ---------------------------------------------------------------------------
// Scratch (device globals — no allocations allowed)
// ---------------------------------------------------------------------------
__device__ float g_ada  [BB * D6];
__device__ float g_ada_c[BB * D6];
__device__ float g_qkv  [BB * NN  * 3 * DD];
__device__ float g_qkv_c[BB * NCC * 3 * DD];
__device__ float g_x1   [BB * NN  * DD];
__device__ float g_c1   [BB * NCC * DD];

// split-bf16 activations (producers write hi/lo pairs)
__device__ __nv_bfloat16 g_xt_h  [BB * NN  * DD],  g_xt_l  [BB * NN  * DD];
__device__ __nv_bfloat16 g_ct_h  [BB * NCC * DD],  g_ct_l  [BB * NCC * DD];
__device__ __nv_bfloat16 g_ax_h  [BB * NN  * DD],  g_ax_l  [BB * NN  * DD];
__device__ __nv_bfloat16 g_acnd_h[BB * NCC * DD],  g_acnd_l[BB * NCC * DD];
__device__ __nv_bfloat16 g_h_h   [BB * NN  * DFF_],g_h_l   [BB * NN  * DFF_];
__device__ __nv_bfloat16 g_hc_h  [BB * NCC * DFF_],g_hc_l  [BB * NCC * DFF_];

// bf16 split weights, transposed to [N][K]
__device__ __nv_bfloat16 g_wqkv_h [3 * DD * DD], g_wqkv_l [3 * DD * DD];
__device__ __nv_bfloat16 g_wqkvc_h[3 * DD * DD], g_wqkvc_l[3 * DD * DD];
__device__ __nv_bfloat16 g_wproj_h[DD * DD],     g_wproj_l[DD * DD];
__device__ __nv_bfloat16 g_wprojc_h[DD * DD],    g_wprojc_l[DD * DD];
__device__ __nv_bfloat16 g_wfc1_h [DD * DFF_],   g_wfc1_l [DD * DFF_];
__device__ __nv_bfloat16 g_wfc1c_h[DD * DFF_],   g_wfc1c_l[DD * DFF_];
__device__ __nv_bfloat16 g_wfc2_h [DFF_ * DD],   g_wfc2_l [DFF_ * DD];
__device__ __nv_bfloat16 g_wfc2c_h[DFF_ * DD],   g_wfc2c_l[DFF_ * DD];

// ---------------------------------------------------------------------------
// Paired weight convert+transpose: z selects (W0,hi0,lo0) vs (W1,hi1,lo1)
// ---------------------------------------------------------------------------
__global__ void wconv2_kernel(const float* __restrict__ W0, __nv_bfloat16* __restrict__ hi0,
                              __nv_bfloat16* __restrict__ lo0,
                              const float* __restrict__ W1, __nv_bfloat16* __restrict__ hi1,
                              __nv_bfloat16* __restrict__ lo1, int K, int N)
{
    const float* W = blockIdx.z ? W1 : W0;
    __nv_bfloat16* hi = blockIdx.z ? hi1 : hi0;
    __nv_bfloat16* lo = blockIdx.z ? lo1 : lo0;
    __shared__ float t[32][33];
    int k0 = blockIdx.y * 32, n0 = blockIdx.x * 32;
    int tx = threadIdx.x, ty = threadIdx.y;
#pragma unroll
    for (int i = 0; i < 32; i += 8)
        t[ty + i][tx] = W[(size_t)(k0 + ty + i) * N + n0 + tx];
    __syncthreads();
#pragma unroll
    for (int i = 0; i < 32; i += 8) {
        float v = t[tx][ty + i];
        int n = n0 + ty + i, k = k0 + tx;
        __nv_bfloat16 h = __float2bfloat16(v);
        hi[(size_t)n * K + k] = h;
        lo[(size_t)n * K + k] = __float2bfloat16(v - __bfloat162float(h));
    }
}

// ---------------------------------------------------------------------------
// Paired adaLN: z selects (W0,b0,out0) vs (W1,b1,out1)
// ---------------------------------------------------------------------------
__global__ void ada2_kernel(const float* __restrict__ c,
                            const float* __restrict__ W0, const float* __restrict__ b0,
                            float* __restrict__ o0,
                            const float* __restrict__ W1, const float* __restrict__ b1,
                            float* __restrict__ o1)
{
    const float* W = blockIdx.z ? W1 : W0;
    const float* bias = blockIdx.z ? b1 : b0;
    float* out = blockIdx.z ? o1 : o0;
    int b = blockIdx.y;
    int j = blockIdx.x * 256 + threadIdx.x;
    __shared__ float sc[DD];
    for (int k = threadIdx.x; k < DD; k += 256) {
        float v = c[b * DD + k];
        sc[k] = v / (1.0f + expf(-v));
    }
    __syncthreads();
    float acc = bias[j];
#pragma unroll 8
    for (int k = 0; k < DD; k++)
        acc += sc[k] * W[(size_t)k * D6 + j];
    out[b * D6 + j] = acc;
}

// ---------------------------------------------------------------------------
// Merged LayerNorm + modulate (x rows then cond rows) -> split bf16 hi/lo
// grid: MX + MC blocks
// ---------------------------------------------------------------------------
__global__ void ln2_kernel(const float* __restrict__ x, const float* __restrict__ cond,
                           const float* __restrict__ ada, const float* __restrict__ ada_c,
                           __nv_bfloat16* __restrict__ xh, __nv_bfloat16* __restrict__ xl,
                           __nv_bfloat16* __restrict__ ch, __nv_bfloat16* __restrict__ cl,
                           int sh_off, int sc_off)
{
    int row = blockIdx.x;
    const float* src; const float* adap; __nv_bfloat16 *oh, *ol; int tokens;
    if (row < MX) { src = x;    adap = ada;   oh = xh; ol = xl; tokens = NN; }
    else          { row -= MX; src = cond; adap = ada_c; oh = ch; ol = cl; tokens = NCC; }
    int b = row / tokens;
    const float* xr = src + (size_t)row * DD;
    float v[4];
    float s = 0.f, s2 = 0.f;
#pragma unroll
    for (int i = 0; i < 4; i++) {
        v[i] = xr[threadIdx.x + i * 256];
        s += v[i]; s2 += v[i] * v[i];
    }
#pragma unroll
    for (int o = 16; o; o >>= 1) {
        s  += __shfl_xor_sync(0xffffffffu, s, o);
        s2 += __shfl_xor_sync(0xffffffffu, s2, o);
    }
    __shared__ float ss[8], ss2[8];
    int w = threadIdx.x >> 5, ln = threadIdx.x & 31;
    if (ln == 0) { ss[w] = s; ss2[w] = s2; }
    __syncthreads();
    float S = 0.f, S2 = 0.f;
#pragma unroll
    for (int i = 0; i < 8; i++) { S += ss[i]; S2 += ss2[i]; }
    float mu  = S * (1.0f / DD);
    float var = S2 * (1.0f / DD) - mu * mu;
    float inv = rsqrtf(var + 1e-6f);
    const float* adab = adap + (size_t)b * D6;
#pragma unroll
    for (int i = 0; i < 4; i++) {
        int j = threadIdx.x + i * 256;
        float r = (v[i] - mu) * inv * (1.0f + adab[sc_off + j]) + adab[sh_off + j];
        __nv_bfloat16 h = __float2bfloat16(r);
        oh[(size_t)row * DD + j] = h;
        ol[(size_t)row * DD + j] = __float2bfloat16(r - __bfloat162float(h));
    }
}

// ---------------------------------------------------------------------------
// Merged-stream mma.sync bf16x3 GEMM (x tiles [0,my0), cond tiles [my0,my0+MYC))
// Inner loop identical to validated R12 kernel.
// ---------------------------------------------------------------------------
#define GST 32768
#define GSM_TOTAL (3 * GST)

template <int MODE>
__global__ void __launch_bounds__(256, 2)
mma_gemm(const __nv_bfloat16* __restrict__ Ahi0, const __nv_bfloat16* __restrict__ Alo0,
         const __nv_bfloat16* __restrict__ Bhi0, const __nv_bfloat16* __restrict__ Blo0,
         const float* __restrict__ bias0, const float* __restrict__ res0,
         const float* __restrict__ ada0,
         float* __restrict__ C0, __nv_bfloat16* __restrict__ Ch0, __nv_bfloat16* __restrict__ Cl0,
         int M0, int tokens0,
         const __nv_bfloat16* __restrict__ Ahi1, const __nv_bfloat16* __restrict__ Alo1,
         const __nv_bfloat16* __restrict__ Bhi1, const __nv_bfloat16* __restrict__ Blo1,
         const float* __restrict__ bias1, const float* __restrict__ res1,
         const float* __restrict__ ada1,
         float* __restrict__ C1, __nv_bfloat16* __restrict__ Ch1, __nv_bfloat16* __restrict__ Cl1,
         int M1, int tokens1,
         int my0, int gate_off, int K, int Nn)
{
    extern __shared__ __align__(1024) char smem[];
    uint32_t sb = smem_to_u32(smem);
    int tid = threadIdx.x, wid = tid >> 5, lane = tid & 31;

    bool s1 = (blockIdx.y >= my0);
    int by = s1 ? (blockIdx.y - my0) : blockIdx.y;
    const __nv_bfloat16* Ahi = s1 ? Ahi1 : Ahi0;
    const __nv_bfloat16* Alo = s1 ? Alo1 : Alo0;
    const __nv_bfloat16* Bhi = s1 ? Bhi1 : Bhi0;
    const __nv_bfloat16* Blo = s1 ? Blo1 : Blo0;
    const float* bias = s1 ? bias1 : bias0;
    const float* res  = s1 ? res1  : res0;
    const float* ada  = s1 ? ada1  : ada0;
    float* C = s1 ? C1 : C0;
    __nv_bfloat16* Ch = s1 ? Ch1 : Ch0;
    __nv_bfloat16* Cl = s1 ? Cl1 : Cl0;
    int M = s1 ? M1 : M0;
    int tokens = s1 ? tokens1 : tokens0;

    int bm = by * 128, bn = blockIdx.x * 128;
    int wm = (wid & 3) * 32;
    int wn = (wid >> 2) * 64;

    float acc[2][8][4];
#pragma unroll
    for (int i = 0; i < 2; i++)
#pragma unroll
        for (int j = 0; j < 8; j++)
#pragma unroll
            for (int k = 0; k < 4; k++) acc[i][j][k] = 0.f;

    const int NCHUNK = K >> 5;

    auto cp_stage = [&](int st, int k0) {
        uint32_t base = sb + st * GST;
#pragma unroll
        for (int it = 0; it < 2; it++) {
            int idx = tid + it * 256;
            int row = idx >> 2, c = idx & 3;
            uint32_t sw = SMEM_SWZ32((uint32_t)(row * 64 + c * 16));
            size_t arow = (bm + row < M) ? (size_t)(bm + row) : 0;
            int an = (bm + row < M) ? 16 : 0;
            CP_ASYNC16Z(base + sw,        Ahi + arow * K + k0 + c * 8, an);
            CP_ASYNC16Z(base + 8192 + sw, Alo + arow * K + k0 + c * 8, an);
            CP_ASYNC16(base + 16384 + sw, Bhi + (size_t)(bn + row) * K + k0 + c * 8);
            CP_ASYNC16(base + 24576 + sw, Blo + (size_t)(bn + row) * K + k0 + c * 8);
        }
        CP_COMMIT();
    };

    auto aaddr = [&](uint32_t abase, int mt, int ks) {
        int row = wm + mt * 16 + (lane & 15);
        uint32_t off = (uint32_t)(row * 64 + ks * 32 + ((lane >> 4) << 4));
        return abase + SMEM_SWZ32(off);
    };
    auto baddr = [&](uint32_t bbase, int p, int ks) {
        int sub = lane >> 3;
        int n = wn + p * 16 + (lane & 7) + ((sub >> 1) << 3);
        uint32_t off = (uint32_t)(n * 64 + ks * 32 + ((sub & 1) << 4));
        return bbase + SMEM_SWZ32(off);
    };

    auto compute = [&](int st) {
        uint32_t aHi = sb + st * GST, aLo = aHi + 8192;
        uint32_t bHi = aHi + 16384,   bLo = aHi + 24576;
#pragma unroll
        for (int ks = 0; ks < 2; ks++) {
            uint32_t afr[2][4], bfr[8][2];
#pragma unroll
            for (int mt = 0; mt < 2; mt++) ldsm4(afr[mt], aaddr(aHi, mt, ks));
#pragma unroll
            for (int p = 0; p < 4; p++) {
                uint32_t t[4]; ldsm4(t, baddr(bHi, p, ks));
                bfr[2*p][0] = t[0]; bfr[2*p][1] = t[1];
                bfr[2*p+1][0] = t[2]; bfr[2*p+1][1] = t[3];
            }
#pragma unroll
            for (int mt = 0; mt < 2; mt++)
#pragma unroll
                for (int nt = 0; nt < 8; nt++) mma16816(acc[mt][nt], afr[mt], bfr[nt]);
#pragma unroll
            for (int mt = 0; mt < 2; mt++) ldsm4(afr[mt], aaddr(aLo, mt, ks));
#pragma unroll
            for (int mt = 0; mt < 2; mt++)
#pragma unroll
                for (int nt = 0; nt < 8; nt++) mma16816(acc[mt][nt], afr[mt], bfr[nt]);
#pragma unroll
            for (int mt = 0; mt < 2; mt++) ldsm4(afr[mt], aaddr(aHi, mt, ks));
#pragma unroll
            for (int p = 0; p < 4; p++) {
                uint32_t t[4]; ldsm4(t, baddr(bLo, p, ks));
                bfr[2*p][0] = t[0]; bfr[2*p][1] = t[1];
                bfr[2*p+1][0] = t[2]; bfr[2*p+1][1] = t[3];
            }
#pragma unroll
            for (int mt = 0; mt < 2; mt++)
#pragma unroll
                for (int nt = 0; nt < 8; nt++) mma16816(acc[mt][nt], afr[mt], bfr[nt]);
        }
    };

    cp_stage(0, 0);
    cp_stage(1, 32);

    for (int i = 0; i < NCHUNK; i++) {
        if (i + 2 < NCHUNK) { CP_WAIT1(); } else { CP_WAIT0(); }
        __syncthreads();
        if (i + 2 < NCHUNK) cp_stage((i + 2) % 3, (i + 2) * 32);
        compute(i % 3);
    }

    int r0 = bm + wm + (lane >> 2);
    int c0 = bn + wn + (lane & 3) * 2;
#pragma unroll
    for (int mt = 0; mt < 2; mt++) {
#pragma unroll
        for (int h = 0; h < 2; h++) {
            int row = r0 + mt * 16 + h * 8;
            if (row >= M) continue;
            int b = row / tokens;
            size_t rb = (size_t)row * Nn;
#pragma unroll
            for (int nt = 0; nt < 8; nt++) {
                int col = c0 + nt * 8;
                float v0 = acc[mt][nt][h * 2 + 0] + bias[col];
                float v1 = acc[mt][nt][h * 2 + 1] + bias[col + 1];
                if (MODE == 1) {
                    float t0 = 0.7978845608028654f * (v0 + 0.044715f * v0 * v0 * v0);
                    float t1 = 0.7978845608028654f * (v1 + 0.044715f * v1 * v1 * v1);
                    v0 = 0.5f * v0 * (1.0f + tanhf(t0));
                    v1 = 0.5f * v1 * (1.0f + tanhf(t1));
                    __nv_bfloat16 h0 = __float2bfloat16(v0), h1 = __float2bfloat16(v1);
                    __nv_bfloat16 l0 = __float2bfloat16(v0 - __bfloat162float(h0));
                    __nv_bfloat16 l1 = __float2bfloat16(v1 - __bfloat162float(h1));
                    *(uint32_t*)(Ch + rb + col) = pack_bf2(h0, h1);
                    *(uint32_t*)(Cl + rb + col) = pack_bf2(l0, l1);
                } else {
                    if (MODE == 2) {
                        const float* adab = ada + (size_t)b * D6 + gate_off;
                        v0 = res[rb + col]     + adab[col]     * v0;
                        v1 = res[rb + col + 1] + adab[col + 1] * v1;
                    }
                    float2 o; o.x = v0; o.y = v1;
                    *(float2*)(C + rb + col) = o;
                }
            }
        }
    }
}

// ---------------------------------------------------------------------------
// Attention (fp32 SIMT): QT=16, 512 threads, float4 global loads.
// ---------------------------------------------------------------------------
#define QT 16
#define CK 64
#define ATH 512

__global__ void __launch_bounds__(ATH)
attn_kernel(const float* __restrict__ qkv, const float* __restrict__ qkv_c,
            __nv_bfloat16* __restrict__ axh, __nv_bfloat16* __restrict__ axl,
            __nv_bfloat16* __restrict__ ach, __nv_bfloat16* __restrict__ acl)
{
    int b = blockIdx.z, h = blockIdx.y;
    int q0 = blockIdx.x * QT;
    int tid = threadIdx.x;
    int warp = tid >> 5, lane = tid & 31;

    __shared__ float q_s[QT][HDD];
    __shared__ float k_s[HDD][CK + 1];
    __shared__ float v_s[CK][HDD];
    __shared__ float p_s[QT][CK];

    // Q tile (float4), scaled by 0.125
    for (int idx = tid; idx < QT * HDD / 4; idx += ATH) {
        int qi = idx >> 4, dq = (idx & 15) * 4;
        int s = q0 + qi;
        float4 val = make_float4(0.f, 0.f, 0.f, 0.f);
        if (s < STOT) {
            if (s < NN) val = *(const float4*)(qkv + ((size_t)(b * NN + s)) * 3072 + h * 64 + dq);
            else        val = *(const float4*)(qkv_c + ((size_t)(b * NCC + (s - NN))) * 3072 + h * 64 + dq);
        }
        q_s[qi][dq]     = val.x * 0.125f;
        q_s[qi][dq + 1] = val.y * 0.125f;
        q_s[qi][dq + 2] = val.z * 0.125f;
        q_s[qi][dq + 3] = val.w * 0.125f;
    }
    __syncthreads();

    float m = -INFINITY, l = 0.f;
    float o0 = 0.f, o1 = 0.f;
    int myq = q0 + warp;

    for (int kc = 0; kc < STOT; kc += CK) {
        for (int idx = tid; idx < CK * HDD / 4; idx += ATH) {
            int kk = idx >> 4, dq = (idx & 15) * 4;
            int s = kc + kk;
            float4 kv = make_float4(0.f, 0.f, 0.f, 0.f);
            float4 vv = make_float4(0.f, 0.f, 0.f, 0.f);
            if (s < STOT) {
                const float* src; size_t base;
                if (s < NN) { src = qkv;   base = ((size_t)(b * NN + s)) * 3072; }
                else        { src = qkv_c; base = ((size_t)(b * NCC + (s - NN))) * 3072; }
                kv = *(const float4*)(src + base + 1024 + h * 64 + dq);
                vv = *(const float4*)(src + base + 2048 + h * 64 + dq);
            }
            k_s[dq][kk] = kv.x; k_s[dq + 1][kk] = kv.y;
            k_s[dq + 2][kk] = kv.z; k_s[dq + 3][kk] = kv.w;
            *(float4*)&v_s[kk][dq] = vv;
        }
        __syncthreads();

        int nk = STOT - kc; if (nk > CK) nk = CK;
        float s0 = 0.f, s1 = 0.f;
#pragma unroll 8
        for (int d = 0; d < HDD; d++) {
            float qv = q_s[warp][d];
            s0 += qv * k_s[d][lane];
            s1 += qv * k_s[d][lane + 32];
        }
        if (lane      >= nk) s0 = -INFINITY;
        if (lane + 32 >= nk) s1 = -INFINITY;

        float mloc = fmaxf(s0, s1);
#pragma unroll
        for (int o = 16; o; o >>= 1) mloc = fmaxf(mloc, __shfl_xor_sync(0xffffffffu, mloc, o));
        float mnew = fmaxf(m, mloc);
        float corr = __expf(m - mnew);
        float p0 = __expf(s0 - mnew);
        float p1 = __expf(s1 - mnew);
        float psum = p0 + p1;
#pragma unroll
        for (int o = 16; o; o >>= 1) psum += __shfl_xor_sync(0xffffffffu, psum, o);
        l = l * corr + psum;
        o0 *= corr; o1 *= corr;
        m = mnew;

        p_s[warp][lane] = p0;
        p_s[warp][lane + 32] = p1;
        __syncwarp();
#pragma unroll 4
        for (int k2 = 0; k2 < CK; k2++) {
            float p = p_s[warp][k2];
            o0 += p * v_s[k2][lane];
            o1 += p * v_s[k2][lane + 32];
        }
        __syncthreads();
    }

    if (myq < STOT) {
        float invl = 1.0f / l;
        o0 *= invl; o1 *= invl;
        __nv_bfloat16 h0 = __float2bfloat16(o0), h1 = __float2bfloat16(o1);
        __nv_bfloat16 l0 = __float2bfloat16(o0 - __bfloat162float(h0));
        __nv_bfloat16 l1 = __float2bfloat16(o1 - __bfloat162float(h1));
        if (myq < NN) {
            size_t base = ((size_t)(b * NN + myq)) * DD + h * 64;
            axh[base + lane] = h0; axh[base + lane + 32] = h1;
            axl[base + lane] = l0; axl[base + lane + 32] = l1;
        } else {
            size_t base = ((size_t)(b * NCC + (myq - NN))) * DD + h * 64;
            ach[base + lane] = h0; ach[base + lane + 32] = h1;
            acl[base + lane] = l0; acl[base + lane + 32] = l1;
        }
    }
}

// ---------------------------------------------------------------------------
// Launch orchestration (12 launches; big QKV GEMM is launch #4 for ncu)
// ---------------------------------------------------------------------------
extern "C" void kernel_launch(void* const* d_in, const int* in_sizes, int n_in,
                              void* d_out, int out_size)
{
    const float* x       = (const float*)d_in[0];
    const float* cond    = (const float*)d_in[1];
    const float* c       = (const float*)d_in[2];
    const float* W_ada   = (const float*)d_in[3];
    const float* b_ada   = (const float*)d_in[4];
    const float* W_ada_c = (const float*)d_in[5];
    const float* b_ada_c = (const float*)d_in[6];
    const float* W_qkv   = (const float*)d_in[7];
    const float* b_qkv   = (const float*)d_in[8];
    const float* W_proj  = (const float*)d_in[9];
    const float* b_proj  = (const float*)d_in[10];
    const float* W_qkv_c = (const float*)d_in[11];
    const float* b_qkv_c = (const float*)d_in[12];
    const float* W_proj_c= (const float*)d_in[13];
    const float* b_proj_c= (const float*)d_in[14];
    const float* W_fc1   = (const float*)d_in[15];
    const float* b_fc1   = (const float*)d_in[16];
    const float* W_fc2   = (const float*)d_in[17];
    const float* b_fc2   = (const float*)d_in[18];
    const float* W_fc1_c = (const float*)d_in[19];
    const float* b_fc1_c = (const float*)d_in[20];
    const float* W_fc2_c = (const float*)d_in[21];
    const float* b_fc2_c = (const float*)d_in[22];

    float* out   = (float*)d_out;
    float* out_x = out;
    float* out_c = out + (size_t)BB * NN * DD;

    float *ada, *ada_c, *qkv, *qkv_c, *x1, *c1;
    cudaGetSymbolAddress((void**)&ada,   g_ada);
    cudaGetSymbolAddress((void**)&ada_c, g_ada_c);
    cudaGetSymbolAddress((void**)&qkv,   g_qkv);
    cudaGetSymbolAddress((void**)&qkv_c, g_qkv_c);
    cudaGetSymbolAddress((void**)&x1,    g_x1);
    cudaGetSymbolAddress((void**)&c1,    g_c1);

    __nv_bfloat16 *xt_h, *xt_l, *ct_h, *ct_l, *ax_h, *ax_l, *ac_h, *ac_l, *h_h, *h_l, *hc_h, *hc_l;
    cudaGetSymbolAddress((void**)&xt_h, g_xt_h);   cudaGetSymbolAddress((void**)&xt_l, g_xt_l);
    cudaGetSymbolAddress((void**)&ct_h, g_ct_h);   cudaGetSymbolAddress((void**)&ct_l, g_ct_l);
    cudaGetSymbolAddress((void**)&ax_h, g_ax_h);   cudaGetSymbolAddress((void**)&ax_l, g_ax_l);
    cudaGetSymbolAddress((void**)&ac_h, g_acnd_h); cudaGetSymbolAddress((void**)&ac_l, g_acnd_l);
    cudaGetSymbolAddress((void**)&h_h,  g_h_h);    cudaGetSymbolAddress((void**)&h_l,  g_h_l);
    cudaGetSymbolAddress((void**)&hc_h, g_hc_h);   cudaGetSymbolAddress((void**)&hc_l, g_hc_l);

    __nv_bfloat16 *wq_h, *wq_l, *wqc_h, *wqc_l, *wp_h, *wp_l, *wpc_h, *wpc_l;
    __nv_bfloat16 *w1_h, *w1_l, *w1c_h, *w1c_l, *w2_h, *w2_l, *w2c_h, *w2c_l;
    cudaGetSymbolAddress((void**)&wq_h,  g_wqkv_h);  cudaGetSymbolAddress((void**)&wq_l,  g_wqkv_l);
    cudaGetSymbolAddress((void**)&wqc_h, g_wqkvc_h); cudaGetSymbolAddress((void**)&wqc_l, g_wqkvc_l);
    cudaGetSymbolAddress((void**)&wp_h,  g_wproj_h); cudaGetSymbolAddress((void**)&wp_l,  g_wproj_l);
    cudaGetSymbolAddress((void**)&wpc_h, g_wprojc_h);cudaGetSymbolAddress((void**)&wpc_l, g_wprojc_l);
    cudaGetSymbolAddress((void**)&w1_h,  g_wfc1_h);  cudaGetSymbolAddress((void**)&w1_l,  g_wfc1_l);
    cudaGetSymbolAddress((void**)&w1c_h, g_wfc1c_h); cudaGetSymbolAddress((void**)&w1c_l, g_wfc1c_l);
    cudaGetSymbolAddress((void**)&w2_h,  g_wfc2_h);  cudaGetSymbolAddress((void**)&w2_l,  g_wfc2_l);
    cudaGetSymbolAddress((void**)&w2c_h, g_wfc2c_h); cudaGetSymbolAddress((void**)&w2c_l, g_wfc2c_l);

    cudaFuncSetAttribute(mma_gemm<0>, cudaFuncAttributeMaxDynamicSharedMemorySize, GSM_TOTAL);
    cudaFuncSetAttribute(mma_gemm<1>, cudaFuncAttributeMaxDynamicSharedMemorySize, GSM_TOTAL);
    cudaFuncSetAttribute(mma_gemm<2>, cudaFuncAttributeMaxDynamicSharedMemorySize, GSM_TOTAL);

    dim3 wb(32, 8);
    const int MY0 = MX / 128;   // 32
    const int GY  = MY0 + MYC;  // 35

    // #1: qkv weight pair
    wconv2_kernel<<<dim3(3 * DD / 32, DD / 32, 2), wb>>>(W_qkv, wq_h, wq_l, W_qkv_c, wqc_h, wqc_l, DD, 3 * DD);
    // #2: adaLN pair
    ada2_kernel<<<dim3(D6 / 256, BB, 2), 256>>>(c, W_ada, b_ada, ada, W_ada_c, b_ada_c, ada_c);
    // #3: LN+mod (MSA), merged
    ln2_kernel<<<MX + MC, 256>>>(x, cond, ada, ada_c, xt_h, xt_l, ct_h, ct_l, 0, DD);
    // #4: merged QKV GEMM  <-- ncu capture slot
    mma_gemm<0><<<dim3(3 * DD / 128, GY), 256, GSM_TOTAL>>>(
        xt_h, xt_l, wq_h, wq_l, b_qkv, nullptr, nullptr, qkv, nullptr, nullptr, MX, NN,
        ct_h, ct_l, wqc_h, wqc_l, b_qkv_c, nullptr, nullptr, qkv_c, nullptr, nullptr, MC, NCC,
        MY0, 0, DD, 3 * DD);
    // #5-#7: remaining weight pairs
    wconv2_kernel<<<dim3(DD / 32, DD / 32, 2),   wb>>>(W_proj, wp_h, wp_l, W_proj_c, wpc_h, wpc_l, DD, DD);
    wconv2_kernel<<<dim3(DFF_ / 32, DD / 32, 2), wb>>>(W_fc1, w1_h, w1_l, W_fc1_c, w1c_h, w1c_l, DD, DFF_);
    wconv2_kernel<<<dim3(DD / 32, DFF_ / 32, 2), wb>>>(W_fc2, w2_h, w2_l, W_fc2_c, w2c_h, w2c_l, DFF_, DD);
    // #8: attention
    attn_kernel<<<dim3((STOT + QT - 1) / QT, HH, BB), ATH>>>(qkv, qkv_c, ax_h, ax_l, ac_h, ac_l);
    // #9: merged proj + gated residual (g_msa @ 2D)
    mma_gemm<2><<<dim3(DD / 128, GY), 256, GSM_TOTAL>>>(
        ax_h, ax_l, wp_h, wp_l, b_proj, x, ada, x1, nullptr, nullptr, MX, NN,
        ac_h, ac_l, wpc_h, wpc_l, b_proj_c, cond, ada_c, c1, nullptr, nullptr, MC, NCC,
        MY0, 2 * DD, DD, DD);
    // #10: LN+mod (MLP), merged
    ln2_kernel<<<MX + MC, 256>>>(x1, c1, ada, ada_c, xt_h, xt_l, ct_h, ct_l, 3 * DD, 4 * DD);
    // #11: merged fc1 + GELU -> split bf16
    mma_gemm<1><<<dim3(DFF_ / 128, GY), 256, GSM_TOTAL>>>(
        xt_h, xt_l, w1_h, w1_l, b_fc1, nullptr, nullptr, nullptr, h_h, h_l, MX, NN,
        ct_h, ct_l, w1c_h, w1c_l, b_fc1_c, nullptr, nullptr, nullptr, hc_h, hc_l, MC, NCC,
        MY0, 0, DD, DFF_);
    // #12: merged fc2 + gated residual (g_mlp @ 5D) -> final outputs
    mma_gemm<2><<<dim3(DD / 128, GY), 256, GSM_TOTAL>>>(
        h_h, h_l, w2_h, w2_l, b_fc2, x1, ada, out_x, nullptr, nullptr, MX, NN,
        hc_h, hc_l, w2c_h, w2c_l, b_fc2_c, c1, ada_c, out_c, nullptr, nullptr, MC, NCC,
        MY0, 5 * DD, DFF_, DD);
}

// round 17
// speedup vs baseline: 4.8973x; 2.1021x over previous
#include <cuda_runtime.h>
#include <cuda_bf16.h>
#include <math.h>
#include <stdint.h>

// Problem constants
#define BB   4
#define NN   1024
#define NCC  77
#define DD   1024
#define HH   16
#define HDD  64
#define DFF_ 4096
#define STOT (NN + NCC)   // 1101
#define D6   (6 * DD)
#define MX   (BB * NN)    // 4096
#define MC   (BB * NCC)   // 308
#define MYC  3            // ceil(308/128)

__device__ __forceinline__ uint32_t smem_to_u32(const void* p) {
    uint32_t a;
    asm("{ .reg .u64 t; cvta.to.shared.u64 t, %1; cvt.u32.u64 %0, t; }" : "=r"(a) : "l"(p));
    return a;
}

// swizzles: 64B rows (GEMM) and 128B rows (attention)
#define SMEM_SWZ32(off) ((off) ^ (((off) >> 3) & 0x30))
#define SMEM_SWZ(off)   ((off) ^ (((off) >> 3) & 0x70))

// ---- base-target (sm_80+) tensor-core primitives: legal on compute_103 ----
__device__ __forceinline__ void ldsm4(uint32_t* r, uint32_t a) {
    asm volatile("ldmatrix.sync.aligned.m8n8.x4.shared.b16 {%0,%1,%2,%3}, [%4];"
                 : "=r"(r[0]), "=r"(r[1]), "=r"(r[2]), "=r"(r[3]) : "r"(a));
}
__device__ __forceinline__ void ldsm4t(uint32_t* r, uint32_t a) {
    asm volatile("ldmatrix.sync.aligned.m8n8.x4.trans.shared.b16 {%0,%1,%2,%3}, [%4];"
                 : "=r"(r[0]), "=r"(r[1]), "=r"(r[2]), "=r"(r[3]) : "r"(a));
}
__device__ __forceinline__ void mma16816(float* d, const uint32_t* a, const uint32_t* b) {
    asm volatile("mma.sync.aligned.m16n8k16.row.col.f32.bf16.bf16.f32 "
                 "{%0,%1,%2,%3},{%4,%5,%6,%7},{%8,%9},{%0,%1,%2,%3};"
                 : "+f"(d[0]), "+f"(d[1]), "+f"(d[2]), "+f"(d[3])
                 : "r"(a[0]), "r"(a[1]), "r"(a[2]), "r"(a[3]), "r"(b[0]), "r"(b[1]));
}
#define CP_ASYNC16(dst, src) \
    asm volatile("cp.async.cg.shared.global [%0], [%1], 16;" :: "r"(dst), "l"(src))
#define CP_ASYNC16Z(dst, src, n) \
    asm volatile("cp.async.cg.shared.global [%0], [%1], 16, %2;" :: "r"(dst), "l"(src), "r"(n))
#define CP_COMMIT() asm volatile("cp.async.commit_group;" ::: "memory")
#define CP_WAIT0()  asm volatile("cp.async.wait_group 0;" ::: "memory")
#define CP_WAIT1()  asm volatile("cp.async.wait_group 1;" ::: "memory")

__device__ __forceinline__ uint32_t pack_bf2(__nv_bfloat16 a, __nv_bfloat16 b) {
    __nv_bfloat162 t = __halves2bfloat162(a, b);
    return *reinterpret_cast<uint32_t*>(&t);
}

// ---------------------------------------------------------------------------
// Scratch (device globals — no allocations allowed)
// ---------------------------------------------------------------------------
__device__ float g_ada  [BB * D6];
__device__ float g_ada_c[BB * D6];
__device__ float g_x1   [BB * NN  * DD];
__device__ float g_c1   [BB * NCC * DD];

// split-bf16 activations
__device__ __nv_bfloat16 g_xt_h  [BB * NN  * DD],  g_xt_l  [BB * NN  * DD];
__device__ __nv_bfloat16 g_ct_h  [BB * NCC * DD],  g_ct_l  [BB * NCC * DD];
__device__ __nv_bfloat16 g_qkv_h [BB * NN  * 3 * DD], g_qkv_l [BB * NN  * 3 * DD];
__device__ __nv_bfloat16 g_qkvc_h[BB * NCC * 3 * DD], g_qkvc_l[BB * NCC * 3 * DD];
__device__ __nv_bfloat16 g_ax_h  [BB * NN  * DD],  g_ax_l  [BB * NN  * DD];
__device__ __nv_bfloat16 g_acnd_h[BB * NCC * DD],  g_acnd_l[BB * NCC * DD];
__device__ __nv_bfloat16 g_h_h   [BB * NN  * DFF_],g_h_l   [BB * NN  * DFF_];
__device__ __nv_bfloat16 g_hc_h  [BB * NCC * DFF_],g_hc_l  [BB * NCC * DFF_];

// bf16 split weights, transposed to [N][K]
__device__ __nv_bfloat16 g_wqkv_h [3 * DD * DD], g_wqkv_l [3 * DD * DD];
__device__ __nv_bfloat16 g_wqkvc_h[3 * DD * DD], g_wqkvc_l[3 * DD * DD];
__device__ __nv_bfloat16 g_wproj_h[DD * DD],     g_wproj_l[DD * DD];
__device__ __nv_bfloat16 g_wprojc_h[DD * DD],    g_wprojc_l[DD * DD];
__device__ __nv_bfloat16 g_wfc1_h [DD * DFF_],   g_wfc1_l [DD * DFF_];
__device__ __nv_bfloat16 g_wfc1c_h[DD * DFF_],   g_wfc1c_l[DD * DFF_];
__device__ __nv_bfloat16 g_wfc2_h [DFF_ * DD],   g_wfc2_l [DFF_ * DD];
__device__ __nv_bfloat16 g_wfc2c_h[DFF_ * DD],   g_wfc2c_l[DFF_ * DD];

// ---------------------------------------------------------------------------
// Paired weight convert+transpose
// ---------------------------------------------------------------------------
__global__ void wconv2_kernel(const float* __restrict__ W0, __nv_bfloat16* __restrict__ hi0,
                              __nv_bfloat16* __restrict__ lo0,
                              const float* __restrict__ W1, __nv_bfloat16* __restrict__ hi1,
                              __nv_bfloat16* __restrict__ lo1, int K, int N)
{
    const float* W = blockIdx.z ? W1 : W0;
    __nv_bfloat16* hi = blockIdx.z ? hi1 : hi0;
    __nv_bfloat16* lo = blockIdx.z ? lo1 : lo0;
    __shared__ float t[32][33];
    int k0 = blockIdx.y * 32, n0 = blockIdx.x * 32;
    int tx = threadIdx.x, ty = threadIdx.y;
#pragma unroll
    for (int i = 0; i < 32; i += 8)
        t[ty + i][tx] = W[(size_t)(k0 + ty + i) * N + n0 + tx];
    __syncthreads();
#pragma unroll
    for (int i = 0; i < 32; i += 8) {
        float v = t[tx][ty + i];
        int n = n0 + ty + i, k = k0 + tx;
        __nv_bfloat16 h = __float2bfloat16(v);
        hi[(size_t)n * K + k] = h;
        lo[(size_t)n * K + k] = __float2bfloat16(v - __bfloat162float(h));
    }
}

// ---------------------------------------------------------------------------
// Paired adaLN
// ---------------------------------------------------------------------------
__global__ void ada2_kernel(const float* __restrict__ c,
                            const float* __restrict__ W0, const float* __restrict__ b0,
                            float* __restrict__ o0,
                            const float* __restrict__ W1, const float* __restrict__ b1,
                            float* __restrict__ o1)
{
    const float* W = blockIdx.z ? W1 : W0;
    const float* bias = blockIdx.z ? b1 : b0;
    float* out = blockIdx.z ? o1 : o0;
    int b = blockIdx.y;
    int j = blockIdx.x * 256 + threadIdx.x;
    __shared__ float sc[DD];
    for (int k = threadIdx.x; k < DD; k += 256) {
        float v = c[b * DD + k];
        sc[k] = v / (1.0f + expf(-v));
    }
    __syncthreads();
    float acc = bias[j];
#pragma unroll 8
    for (int k = 0; k < DD; k++)
        acc += sc[k] * W[(size_t)k * D6 + j];
    out[b * D6 + j] = acc;
}

// ---------------------------------------------------------------------------
// Merged LayerNorm + modulate -> split bf16
// ---------------------------------------------------------------------------
__global__ void ln2_kernel(const float* __restrict__ x, const float* __restrict__ cond,
                           const float* __restrict__ ada, const float* __restrict__ ada_c,
                           __nv_bfloat16* __restrict__ xh, __nv_bfloat16* __restrict__ xl,
                           __nv_bfloat16* __restrict__ ch, __nv_bfloat16* __restrict__ cl,
                           int sh_off, int sc_off)
{
    int row = blockIdx.x;
    const float* src; const float* adap; __nv_bfloat16 *oh, *ol; int tokens;
    if (row < MX) { src = x;    adap = ada;   oh = xh; ol = xl; tokens = NN; }
    else          { row -= MX; src = cond; adap = ada_c; oh = ch; ol = cl; tokens = NCC; }
    int b = row / tokens;
    const float* xr = src + (size_t)row * DD;
    float v[4];
    float s = 0.f, s2 = 0.f;
#pragma unroll
    for (int i = 0; i < 4; i++) {
        v[i] = xr[threadIdx.x + i * 256];
        s += v[i]; s2 += v[i] * v[i];
    }
#pragma unroll
    for (int o = 16; o; o >>= 1) {
        s  += __shfl_xor_sync(0xffffffffu, s, o);
        s2 += __shfl_xor_sync(0xffffffffu, s2, o);
    }
    __shared__ float ss[8], ss2[8];
    int w = threadIdx.x >> 5, ln = threadIdx.x & 31;
    if (ln == 0) { ss[w] = s; ss2[w] = s2; }
    __syncthreads();
    float S = 0.f, S2 = 0.f;
#pragma unroll
    for (int i = 0; i < 8; i++) { S += ss[i]; S2 += ss2[i]; }
    float mu  = S * (1.0f / DD);
    float var = S2 * (1.0f / DD) - mu * mu;
    float inv = rsqrtf(var + 1e-6f);
    const float* adab = adap + (size_t)b * D6;
#pragma unroll
    for (int i = 0; i < 4; i++) {
        int j = threadIdx.x + i * 256;
        float r = (v[i] - mu) * inv * (1.0f + adab[sc_off + j]) + adab[sh_off + j];
        __nv_bfloat16 h = __float2bfloat16(r);
        oh[(size_t)row * DD + j] = h;
        ol[(size_t)row * DD + j] = __float2bfloat16(r - __bfloat162float(h));
    }
}

// ---------------------------------------------------------------------------
// Merged-stream mma.sync bf16x3 GEMM.  MODE 0: fp32+bias; MODE 1: gelu->bf16 h/l;
// MODE 2: fp32 res+gate; MODE 3: bias->bf16 h/l.
// ---------------------------------------------------------------------------
#define GST 32768
#define GSM_TOTAL (3 * GST)

template <int MODE>
__global__ void __launch_bounds__(256, 2)
mma_gemm(const __nv_bfloat16* __restrict__ Ahi0, const __nv_bfloat16* __restrict__ Alo0,
         const __nv_bfloat16* __restrict__ Bhi0, const __nv_bfloat16* __restrict__ Blo0,
         const float* __restrict__ bias0, const float* __restrict__ res0,
         const float* __restrict__ ada0,
         float* __restrict__ C0, __nv_bfloat16* __restrict__ Ch0, __nv_bfloat16* __restrict__ Cl0,
         int M0, int tokens0,
         const __nv_bfloat16* __restrict__ Ahi1, const __nv_bfloat16* __restrict__ Alo1,
         const __nv_bfloat16* __restrict__ Bhi1, const __nv_bfloat16* __restrict__ Blo1,
         const float* __restrict__ bias1, const float* __restrict__ res1,
         const float* __restrict__ ada1,
         float* __restrict__ C1, __nv_bfloat16* __restrict__ Ch1, __nv_bfloat16* __restrict__ Cl1,
         int M1, int tokens1,
         int my0, int gate_off, int K, int Nn)
{
    extern __shared__ __align__(1024) char smem[];
    uint32_t sb = smem_to_u32(smem);
    int tid = threadIdx.x, wid = tid >> 5, lane = tid & 31;

    bool s1 = (blockIdx.y >= my0);
    int by = s1 ? (blockIdx.y - my0) : blockIdx.y;
    const __nv_bfloat16* Ahi = s1 ? Ahi1 : Ahi0;
    const __nv_bfloat16* Alo = s1 ? Alo1 : Alo0;
    const __nv_bfloat16* Bhi = s1 ? Bhi1 : Bhi0;
    const __nv_bfloat16* Blo = s1 ? Blo1 : Blo0;
    const float* bias = s1 ? bias1 : bias0;
    const float* res  = s1 ? res1  : res0;
    const float* ada  = s1 ? ada1  : ada0;
    float* C = s1 ? C1 : C0;
    __nv_bfloat16* Ch = s1 ? Ch1 : Ch0;
    __nv_bfloat16* Cl = s1 ? Cl1 : Cl0;
    int M = s1 ? M1 : M0;
    int tokens = s1 ? tokens1 : tokens0;

    int bm = by * 128, bn = blockIdx.x * 128;
    int wm = (wid & 3) * 32;
    int wn = (wid >> 2) * 64;

    float acc[2][8][4];
#pragma unroll
    for (int i = 0; i < 2; i++)
#pragma unroll
        for (int j = 0; j < 8; j++)
#pragma unroll
            for (int k = 0; k < 4; k++) acc[i][j][k] = 0.f;

    const int NCHUNK = K >> 5;

    auto cp_stage = [&](int st, int k0) {
        uint32_t base = sb + st * GST;
#pragma unroll
        for (int it = 0; it < 2; it++) {
            int idx = tid + it * 256;
            int row = idx >> 2, c = idx & 3;
            uint32_t sw = SMEM_SWZ32((uint32_t)(row * 64 + c * 16));
            size_t arow = (bm + row < M) ? (size_t)(bm + row) : 0;
            int an = (bm + row < M) ? 16 : 0;
            CP_ASYNC16Z(base + sw,        Ahi + arow * K + k0 + c * 8, an);
            CP_ASYNC16Z(base + 8192 + sw, Alo + arow * K + k0 + c * 8, an);
            CP_ASYNC16(base + 16384 + sw, Bhi + (size_t)(bn + row) * K + k0 + c * 8);
            CP_ASYNC16(base + 24576 + sw, Blo + (size_t)(bn + row) * K + k0 + c * 8);
        }
        CP_COMMIT();
    };

    auto aaddr = [&](uint32_t abase, int mt, int ks) {
        int row = wm + mt * 16 + (lane & 15);
        uint32_t off = (uint32_t)(row * 64 + ks * 32 + ((lane >> 4) << 4));
        return abase + SMEM_SWZ32(off);
    };
    auto baddr = [&](uint32_t bbase, int p, int ks) {
        int sub = lane >> 3;
        int n = wn + p * 16 + (lane & 7) + ((sub >> 1) << 3);
        uint32_t off = (uint32_t)(n * 64 + ks * 32 + ((sub & 1) << 4));
        return bbase + SMEM_SWZ32(off);
    };

    auto compute = [&](int st) {
        uint32_t aHi = sb + st * GST, aLo = aHi + 8192;
        uint32_t bHi = aHi + 16384,   bLo = aHi + 24576;
#pragma unroll
        for (int ks = 0; ks < 2; ks++) {
            uint32_t afr[2][4], bfr[8][2];
#pragma unroll
            for (int mt = 0; mt < 2; mt++) ldsm4(afr[mt], aaddr(aHi, mt, ks));
#pragma unroll
            for (int p = 0; p < 4; p++) {
                uint32_t t[4]; ldsm4(t, baddr(bHi, p, ks));
                bfr[2*p][0] = t[0]; bfr[2*p][1] = t[1];
                bfr[2*p+1][0] = t[2]; bfr[2*p+1][1] = t[3];
            }
#pragma unroll
            for (int mt = 0; mt < 2; mt++)
#pragma unroll
                for (int nt = 0; nt < 8; nt++) mma16816(acc[mt][nt], afr[mt], bfr[nt]);
#pragma unroll
            for (int mt = 0; mt < 2; mt++) ldsm4(afr[mt], aaddr(aLo, mt, ks));
#pragma unroll
            for (int mt = 0; mt < 2; mt++)
#pragma unroll
                for (int nt = 0; nt < 8; nt++) mma16816(acc[mt][nt], afr[mt], bfr[nt]);
#pragma unroll
            for (int mt = 0; mt < 2; mt++) ldsm4(afr[mt], aaddr(aHi, mt, ks));
#pragma unroll
            for (int p = 0; p < 4; p++) {
                uint32_t t[4]; ldsm4(t, baddr(bLo, p, ks));
                bfr[2*p][0] = t[0]; bfr[2*p][1] = t[1];
                bfr[2*p+1][0] = t[2]; bfr[2*p+1][1] = t[3];
            }
#pragma unroll
            for (int mt = 0; mt < 2; mt++)
#pragma unroll
                for (int nt = 0; nt < 8; nt++) mma16816(acc[mt][nt], afr[mt], bfr[nt]);
        }
    };

    cp_stage(0, 0);
    cp_stage(1, 32);

    for (int i = 0; i < NCHUNK; i++) {
        if (i + 2 < NCHUNK) { CP_WAIT1(); } else { CP_WAIT0(); }
        __syncthreads();
        if (i + 2 < NCHUNK) cp_stage((i + 2) % 3, (i + 2) * 32);
        compute(i % 3);
    }

    int r0 = bm + wm + (lane >> 2);
    int c0 = bn + wn + (lane & 3) * 2;
#pragma unroll
    for (int mt = 0; mt < 2; mt++) {
#pragma unroll
        for (int h = 0; h < 2; h++) {
            int row = r0 + mt * 16 + h * 8;
            if (row >= M) continue;
            int b = row / tokens;
            size_t rb = (size_t)row * Nn;
#pragma unroll
            for (int nt = 0; nt < 8; nt++) {
                int col = c0 + nt * 8;
                float v0 = acc[mt][nt][h * 2 + 0] + bias[col];
                float v1 = acc[mt][nt][h * 2 + 1] + bias[col + 1];
                if (MODE == 1 || MODE == 3) {
                    if (MODE == 1) {
                        float t0 = 0.7978845608028654f * (v0 + 0.044715f * v0 * v0 * v0);
                        float t1 = 0.7978845608028654f * (v1 + 0.044715f * v1 * v1 * v1);
                        v0 = 0.5f * v0 * (1.0f + tanhf(t0));
                        v1 = 0.5f * v1 * (1.0f + tanhf(t1));
                    }
                    __nv_bfloat16 h0 = __float2bfloat16(v0), h1 = __float2bfloat16(v1);
                    __nv_bfloat16 l0 = __float2bfloat16(v0 - __bfloat162float(h0));
                    __nv_bfloat16 l1 = __float2bfloat16(v1 - __bfloat162float(h1));
                    *(uint32_t*)(Ch + rb + col) = pack_bf2(h0, h1);
                    *(uint32_t*)(Cl + rb + col) = pack_bf2(l0, l1);
                } else {
                    if (MODE == 2) {
                        const float* adab = ada + (size_t)b * D6 + gate_off;
                        v0 = res[rb + col]     + adab[col]     * v0;
                        v1 = res[rb + col + 1] + adab[col + 1] * v1;
                    }
                    float2 o; o.x = v0; o.y = v1;
                    *(float2*)(C + rb + col) = o;
                }
            }
        }
    }
}

// ---------------------------------------------------------------------------
// mma.sync flash attention: 64 queries/block, 18 chunks of 64 keys,
// 256 threads = 8 warps (4M x 2N).  bf16x3 QK^T and PV, fp32 softmax.
// smem: Qh 0, Ql 8192, stages@16384 (Kh,Kl,Vh,Vl 8KB each, 32KB/stage, x2),
// Ph 81920, Pl 90112, m_red 98304, l_red 98816.  Total 99328 B.
// ---------------------------------------------------------------------------
#define AQT 64
#define ANCH 18
#define ASM_ST  16384
#define AST     32768
#define ASM_P   (ASM_ST + 2 * AST)
#define ASM_PL  (ASM_P + 8192)
#define ASM_MR  (ASM_P + 16384)
#define ASM_LR  (ASM_MR + 512)
#define ASM_TOT (ASM_LR + 512)

__global__ void __launch_bounds__(256, 2)
attn_mma(const __nv_bfloat16* __restrict__ qh, const __nv_bfloat16* __restrict__ ql,
         const __nv_bfloat16* __restrict__ qch, const __nv_bfloat16* __restrict__ qcl,
         __nv_bfloat16* __restrict__ axh, __nv_bfloat16* __restrict__ axl,
         __nv_bfloat16* __restrict__ ach, __nv_bfloat16* __restrict__ acl)
{
    extern __shared__ __align__(1024) char smem[];
    uint32_t sb = smem_to_u32(smem);
    int b = blockIdx.z, h = blockIdx.y;
    int q0 = blockIdx.x * AQT;
    int tid = threadIdx.x, wid = tid >> 5, lane = tid & 31;
    int wm = (wid & 3) * 16;
    int wn = (wid >> 2) * 32;
    int wnI = wid >> 2;
    float* m_red = (float*)(smem + ASM_MR);
    float* l_red = (float*)(smem + ASM_LR);

    // per-row source select (token t of the joint sequence)
    auto src_off = [&](int t, const __nv_bfloat16** ph, const __nv_bfloat16** pl, int* an) {
        if (t < NN)        { *ph = qh;  *pl = ql;  *an = 16; return (size_t)(b * NN + t) * 3072 + h * 64; }
        else if (t < STOT) { *ph = qch; *pl = qcl; *an = 16; return (size_t)(b * NCC + (t - NN)) * 3072 + h * 64; }
        else               { *ph = qh;  *pl = ql;  *an = 0;  return (size_t)0; }
    };

    // Q load (once)
#pragma unroll
    for (int it = 0; it < 2; it++) {
        int idx = tid + it * 256;
        int row = idx >> 3, slot = idx & 7;
        const __nv_bfloat16 *sh_, *sl_; int an;
        size_t off = src_off(q0 + row, &sh_, &sl_, &an);
        uint32_t sw = SMEM_SWZ((uint32_t)(row * 128 + slot * 16));
        CP_ASYNC16Z(sb + sw,        sh_ + off + slot * 8, an);
        CP_ASYNC16Z(sb + 8192 + sw, sl_ + off + slot * 8, an);
    }
    CP_COMMIT();

    auto load_kv = [&](int st, int kc) {
        uint32_t base = sb + ASM_ST + st * AST;
#pragma unroll
        for (int it = 0; it < 2; it++) {
            int idx = tid + it * 256;
            int row = idx >> 3, slot = idx & 7;
            const __nv_bfloat16 *sh_, *sl_; int an;
            size_t off = src_off(kc + row, &sh_, &sl_, &an);
            uint32_t sw = SMEM_SWZ((uint32_t)(row * 128 + slot * 16));
            CP_ASYNC16Z(base + sw,         sh_ + off + 1024 + slot * 8, an);
            CP_ASYNC16Z(base + 8192 + sw,  sl_ + off + 1024 + slot * 8, an);
            CP_ASYNC16Z(base + 16384 + sw, sh_ + off + 2048 + slot * 8, an);
            CP_ASYNC16Z(base + 24576 + sw, sl_ + off + 2048 + slot * 8, an);
        }
        CP_COMMIT();
    };
    load_kv(0, 0);

    // fragment address helpers (128B rows)
    auto aaddrA = [&](uint32_t base, int ks) {   // A rows wm..wm+15
        int row = wm + (lane & 15);
        return base + SMEM_SWZ((uint32_t)(row * 128 + ks * 32 + ((lane >> 4) << 4)));
    };
    auto baddrB = [&](uint32_t base, int p, int ks) {   // B rows = keys wn + p*16 ..
        int sub = lane >> 3;
        int n = wn + p * 16 + (lane & 7) + ((sub >> 1) << 3);
        return base + SMEM_SWZ((uint32_t)(n * 128 + ks * 32 + ((sub & 1) << 4)));
    };
    auto vaddrT = [&](uint32_t base, int p, int ks) {   // trans: rows = keys, cols = dims wn + p*16
        int row = ks * 16 + (lane & 15);
        return base + SMEM_SWZ((uint32_t)(row * 128 + (wn + p * 16) * 2 + ((lane >> 4) << 4)));
    };

    float m0 = -INFINITY, m1 = -INFINITY, l0 = 0.f, l1 = 0.f;
    float acc_o[4][4];
#pragma unroll
    for (int nt = 0; nt < 4; nt++)
#pragma unroll
        for (int c = 0; c < 4; c++) acc_o[nt][c] = 0.f;

    int row0 = wm + (lane >> 2), row1 = row0 + 8;

    for (int i = 0; i < ANCH; i++) {
        CP_WAIT0();
        __syncthreads();
        if (i + 1 < ANCH) load_kv((i + 1) & 1, (i + 1) * 64);
        uint32_t kb = sb + ASM_ST + (i & 1) * AST;

        // ---- QK^T (3 products) ----
        float accs[4][4];
#pragma unroll
        for (int nt = 0; nt < 4; nt++)
#pragma unroll
            for (int c = 0; c < 4; c++) accs[nt][c] = 0.f;
#pragma unroll
        for (int ks = 0; ks < 4; ks++) {
            uint32_t ah[4], al[4], bf[4][2];
            ldsm4(ah, aaddrA(sb, ks));
            ldsm4(al, aaddrA(sb + 8192, ks));
#pragma unroll
            for (int p = 0; p < 2; p++) {
                uint32_t t[4]; ldsm4(t, baddrB(kb, p, ks));
                bf[2*p][0] = t[0]; bf[2*p][1] = t[1];
                bf[2*p+1][0] = t[2]; bf[2*p+1][1] = t[3];
            }
#pragma unroll
            for (int nt = 0; nt < 4; nt++) mma16816(accs[nt], ah, bf[nt]);
#pragma unroll
            for (int nt = 0; nt < 4; nt++) mma16816(accs[nt], al, bf[nt]);
#pragma unroll
            for (int p = 0; p < 2; p++) {
                uint32_t t[4]; ldsm4(t, baddrB(kb + 8192, p, ks));
                bf[2*p][0] = t[0]; bf[2*p][1] = t[1];
                bf[2*p+1][0] = t[2]; bf[2*p+1][1] = t[3];
            }
#pragma unroll
            for (int nt = 0; nt < 4; nt++) mma16816(accs[nt], ah, bf[nt]);
        }

        // scale + mask
        int kc = i * 64;
#pragma unroll
        for (int nt = 0; nt < 4; nt++) {
            int col = kc + wn + nt * 8 + (lane & 3) * 2;
            bool ok0 = (col < STOT), ok1 = (col + 1 < STOT);
            accs[nt][0] = ok0 ? accs[nt][0] * 0.125f : -INFINITY;
            accs[nt][1] = ok1 ? accs[nt][1] * 0.125f : -INFINITY;
            accs[nt][2] = ok0 ? accs[nt][2] * 0.125f : -INFINITY;
            accs[nt][3] = ok1 ? accs[nt][3] * 0.125f : -INFINITY;
        }

        // row max (warp 32-key, then cross 2 N-warps)
        float tm0 = -INFINITY, tm1 = -INFINITY;
#pragma unroll
        for (int nt = 0; nt < 4; nt++) {
            tm0 = fmaxf(tm0, fmaxf(accs[nt][0], accs[nt][1]));
            tm1 = fmaxf(tm1, fmaxf(accs[nt][2], accs[nt][3]));
        }
#pragma unroll
        for (int o = 1; o <= 2; o <<= 1) {
            tm0 = fmaxf(tm0, __shfl_xor_sync(0xffffffffu, tm0, o));
            tm1 = fmaxf(tm1, __shfl_xor_sync(0xffffffffu, tm1, o));
        }
        if ((lane & 3) == 0) { m_red[wnI * 64 + row0] = tm0; m_red[wnI * 64 + row1] = tm1; }
        __syncthreads();
        float mn0 = fmaxf(m0, fmaxf(m_red[row0], m_red[64 + row0]));
        float mn1 = fmaxf(m1, fmaxf(m_red[row1], m_red[64 + row1]));

        // exp, P store, local sums
        float ls0 = 0.f, ls1 = 0.f;
#pragma unroll
        for (int nt = 0; nt < 4; nt++) {
            float p0 = __expf(accs[nt][0] - mn0);
            float p1 = __expf(accs[nt][1] - mn0);
            float p2 = __expf(accs[nt][2] - mn1);
            float p3 = __expf(accs[nt][3] - mn1);
            ls0 += p0 + p1; ls1 += p2 + p3;
            int colb = (wn + nt * 8 + (lane & 3) * 2) * 2;   // byte col
            uint32_t off0 = SMEM_SWZ((uint32_t)(row0 * 128 + colb));
            uint32_t off1 = SMEM_SWZ((uint32_t)(row1 * 128 + colb));
            __nv_bfloat16 h0 = __float2bfloat16(p0), h1 = __float2bfloat16(p1);
            __nv_bfloat16 h2 = __float2bfloat16(p2), h3 = __float2bfloat16(p3);
            __nv_bfloat16 e0 = __float2bfloat16(p0 - __bfloat162float(h0));
            __nv_bfloat16 e1 = __float2bfloat16(p1 - __bfloat162float(h1));
            __nv_bfloat16 e2 = __float2bfloat16(p2 - __bfloat162float(h2));
            __nv_bfloat16 e3 = __float2bfloat16(p3 - __bfloat162float(h3));
            *(uint32_t*)(smem + ASM_P  + off0) = pack_bf2(h0, h1);
            *(uint32_t*)(smem + ASM_PL + off0) = pack_bf2(e0, e1);
            *(uint32_t*)(smem + ASM_P  + off1) = pack_bf2(h2, h3);
            *(uint32_t*)(smem + ASM_PL + off1) = pack_bf2(e2, e3);
        }
#pragma unroll
        for (int o = 1; o <= 2; o <<= 1) {
            ls0 += __shfl_xor_sync(0xffffffffu, ls0, o);
            ls1 += __shfl_xor_sync(0xffffffffu, ls1, o);
        }
        if ((lane & 3) == 0) { l_red[wnI * 64 + row0] = ls0; l_red[wnI * 64 + row1] = ls1; }
        __syncthreads();

        float corr0 = __expf(m0 - mn0);
        float corr1 = __expf(m1 - mn1);
        l0 = l0 * corr0 + l_red[row0] + l_red[64 + row0];
        l1 = l1 * corr1 + l_red[row1] + l_red[64 + row1];
        m0 = mn0; m1 = mn1;
#pragma unroll
        for (int nt = 0; nt < 4; nt++) {
            acc_o[nt][0] *= corr0; acc_o[nt][1] *= corr0;
            acc_o[nt][2] *= corr1; acc_o[nt][3] *= corr1;
        }

        // ---- PV (3 products), V via trans-ldsm ----
#pragma unroll
        for (int ks = 0; ks < 4; ks++) {
            uint32_t ph[4], pl[4], bv[4][2];
            ldsm4(ph, aaddrA(sb + ASM_P, ks));
            ldsm4(pl, aaddrA(sb + ASM_PL, ks));
#pragma unroll
            for (int p = 0; p < 2; p++) {
                uint32_t t[4]; ldsm4t(t, vaddrT(kb + 16384, p, ks));
                bv[2*p][0] = t[0]; bv[2*p][1] = t[1];
                bv[2*p+1][0] = t[2]; bv[2*p+1][1] = t[3];
            }
#pragma unroll
            for (int nt = 0; nt < 4; nt++) mma16816(acc_o[nt], ph, bv[nt]);
#pragma unroll
            for (int nt = 0; nt < 4; nt++) mma16816(acc_o[nt], pl, bv[nt]);
#pragma unroll
            for (int p = 0; p < 2; p++) {
                uint32_t t[4]; ldsm4t(t, vaddrT(kb + 24576, p, ks));
                bv[2*p][0] = t[0]; bv[2*p][1] = t[1];
                bv[2*p+1][0] = t[2]; bv[2*p+1][1] = t[3];
            }
#pragma unroll
            for (int nt = 0; nt < 4; nt++) mma16816(acc_o[nt], ph, bv[nt]);
        }
        __syncthreads();   // protect P/m_red/l_red before next chunk overwrites
    }

    // ---- output ----
    float i0 = 1.0f / l0, i1 = 1.0f / l1;
    int qg0 = q0 + row0, qg1 = q0 + row1;
#pragma unroll
    for (int nt = 0; nt < 4; nt++) {
        int col = h * 64 + wn + nt * 8 + (lane & 3) * 2;
        float a0 = acc_o[nt][0] * i0, a1 = acc_o[nt][1] * i0;
        float a2 = acc_o[nt][2] * i1, a3 = acc_o[nt][3] * i1;
        __nv_bfloat16 h0 = __float2bfloat16(a0), h1 = __float2bfloat16(a1);
        __nv_bfloat16 h2 = __float2bfloat16(a2), h3 = __float2bfloat16(a3);
        __nv_bfloat16 e0 = __float2bfloat16(a0 - __bfloat162float(h0));
        __nv_bfloat16 e1 = __float2bfloat16(a1 - __bfloat162float(h1));
        __nv_bfloat16 e2 = __float2bfloat16(a2 - __bfloat162float(h2));
        __nv_bfloat16 e3 = __float2bfloat16(a3 - __bfloat162float(h3));
        if (qg0 < NN) {
            size_t base = (size_t)(b * NN + qg0) * DD + col;
            *(uint32_t*)(axh + base) = pack_bf2(h0, h1);
            *(uint32_t*)(axl + base) = pack_bf2(e0, e1);
        } else if (qg0 < STOT) {
            size_t base = (size_t)(b * NCC + (qg0 - NN)) * DD + col;
            *(uint32_t*)(ach + base) = pack_bf2(h0, h1);
            *(uint32_t*)(acl + base) = pack_bf2(e0, e1);
        }
        if (qg1 < NN) {
            size_t base = (size_t)(b * NN + qg1) * DD + col;
            *(uint32_t*)(axh + base) = pack_bf2(h2, h3);
            *(uint32_t*)(axl + base) = pack_bf2(e2, e3);
        } else if (qg1 < STOT) {
            size_t base = (size_t)(b * NCC + (qg1 - NN)) * DD + col;
            *(uint32_t*)(ach + base) = pack_bf2(h2, h3);
            *(uint32_t*)(acl + base) = pack_bf2(e2, e3);
        }
    }
}

// ---------------------------------------------------------------------------
// Launch orchestration
// ---------------------------------------------------------------------------
extern "C" void kernel_launch(void* const* d_in, const int* in_sizes, int n_in,
                              void* d_out, int out_size)
{
    const float* x       = (const float*)d_in[0];
    const float* cond    = (const float*)d_in[1];
    const float* c       = (const float*)d_in[2];
    const float* W_ada   = (const float*)d_in[3];
    const float* b_ada   = (const float*)d_in[4];
    const float* W_ada_c = (const float*)d_in[5];
    const float* b_ada_c = (const float*)d_in[6];
    const float* W_qkv   = (const float*)d_in[7];
    const float* b_qkv   = (const float*)d_in[8];
    const float* W_proj  = (const float*)d_in[9];
    const float* b_proj  = (const float*)d_in[10];
    const float* W_qkv_c = (const float*)d_in[11];
    const float* b_qkv_c = (const float*)d_in[12];
    const float* W_proj_c= (const float*)d_in[13];
    const float* b_proj_c= (const float*)d_in[14];
    const float* W_fc1   = (const float*)d_in[15];
    const float* b_fc1   = (const float*)d_in[16];
    const float* W_fc2   = (const float*)d_in[17];
    const float* b_fc2   = (const float*)d_in[18];
    const float* W_fc1_c = (const float*)d_in[19];
    const float* b_fc1_c = (const float*)d_in[20];
    const float* W_fc2_c = (const float*)d_in[21];
    const float* b_fc2_c = (const float*)d_in[22];

    float* out   = (float*)d_out;
    float* out_x = out;
    float* out_c = out + (size_t)BB * NN * DD;

    float *ada, *ada_c, *x1, *c1;
    cudaGetSymbolAddress((void**)&ada,   g_ada);
    cudaGetSymbolAddress((void**)&ada_c, g_ada_c);
    cudaGetSymbolAddress((void**)&x1,    g_x1);
    cudaGetSymbolAddress((void**)&c1,    g_c1);

    __nv_bfloat16 *xt_h, *xt_l, *ct_h, *ct_l, *ax_h, *ax_l, *ac_h, *ac_l, *h_h, *h_l, *hc_h, *hc_l;
    __nv_bfloat16 *qk_h, *qk_l, *qkc_h, *qkc_l;
    cudaGetSymbolAddress((void**)&xt_h, g_xt_h);   cudaGetSymbolAddress((void**)&xt_l, g_xt_l);
    cudaGetSymbolAddress((void**)&ct_h, g_ct_h);   cudaGetSymbolAddress((void**)&ct_l, g_ct_l);
    cudaGetSymbolAddress((void**)&qk_h, g_qkv_h);  cudaGetSymbolAddress((void**)&qk_l, g_qkv_l);
    cudaGetSymbolAddress((void**)&qkc_h, g_qkvc_h);cudaGetSymbolAddress((void**)&qkc_l, g_qkvc_l);
    cudaGetSymbolAddress((void**)&ax_h, g_ax_h);   cudaGetSymbolAddress((void**)&ax_l, g_ax_l);
    cudaGetSymbolAddress((void**)&ac_h, g_acnd_h); cudaGetSymbolAddress((void**)&ac_l, g_acnd_l);
    cudaGetSymbolAddress((void**)&h_h,  g_h_h);    cudaGetSymbolAddress((void**)&h_l,  g_h_l);
    cudaGetSymbolAddress((void**)&hc_h, g_hc_h);   cudaGetSymbolAddress((void**)&hc_l, g_hc_l);

    __nv_bfloat16 *wq_h, *wq_l, *wqc_h, *wqc_l, *wp_h, *wp_l, *wpc_h, *wpc_l;
    __nv_bfloat16 *w1_h, *w1_l, *w1c_h, *w1c_l, *w2_h, *w2_l, *w2c_h, *w2c_l;
    cudaGetSymbolAddress((void**)&wq_h,  g_wqkv_h);  cudaGetSymbolAddress((void**)&wq_l,  g_wqkv_l);
    cudaGetSymbolAddress((void**)&wqc_h, g_wqkvc_h); cudaGetSymbolAddress((void**)&wqc_l, g_wqkvc_l);
    cudaGetSymbolAddress((void**)&wp_h,  g_wproj_h); cudaGetSymbolAddress((void**)&wp_l,  g_wproj_l);
    cudaGetSymbolAddress((void**)&wpc_h, g_wprojc_h);cudaGetSymbolAddress((void**)&wpc_l, g_wprojc_l);
    cudaGetSymbolAddress((void**)&w1_h,  g_wfc1_h);  cudaGetSymbolAddress((void**)&w1_l,  g_wfc1_l);
    cudaGetSymbolAddress((void**)&w1c_h, g_wfc1c_h); cudaGetSymbolAddress((void**)&w1c_l, g_wfc1c_l);
    cudaGetSymbolAddress((void**)&w2_h,  g_wfc2_h);  cudaGetSymbolAddress((void**)&w2_l,  g_wfc2_l);
    cudaGetSymbolAddress((void**)&w2c_h, g_wfc2c_h); cudaGetSymbolAddress((void**)&w2c_l, g_wfc2c_l);

    cudaFuncSetAttribute(mma_gemm<1>, cudaFuncAttributeMaxDynamicSharedMemorySize, GSM_TOTAL);
    cudaFuncSetAttribute(mma_gemm<2>, cudaFuncAttributeMaxDynamicSharedMemorySize, GSM_TOTAL);
    cudaFuncSetAttribute(mma_gemm<3>, cudaFuncAttributeMaxDynamicSharedMemorySize, GSM_TOTAL);
    cudaFuncSetAttribute(attn_mma,    cudaFuncAttributeMaxDynamicSharedMemorySize, ASM_TOT);

    dim3 wb(32, 8);
    const int MY0 = MX / 128;   // 32
    const int GY  = MY0 + MYC;  // 35

    // #1: qkv weight pair
    wconv2_kernel<<<dim3(3 * DD / 32, DD / 32, 2), wb>>>(W_qkv, wq_h, wq_l, W_qkv_c, wqc_h, wqc_l, DD, 3 * DD);
    // #2: adaLN pair
    ada2_kernel<<<dim3(D6 / 256, BB, 2), 256>>>(c, W_ada, b_ada, ada, W_ada_c, b_ada_c, ada_c);
    // #3: LN+mod (MSA), merged
    ln2_kernel<<<MX + MC, 256>>>(x, cond, ada, ada_c, xt_h, xt_l, ct_h, ct_l, 0, DD);
    // #4: merged QKV GEMM -> split bf16 (ncu capture slot)
    mma_gemm<3><<<dim3(3 * DD / 128, GY), 256, GSM_TOTAL>>>(
        xt_h, xt_l, wq_h, wq_l, b_qkv, nullptr, nullptr, nullptr, qk_h, qk_l, MX, NN,
        ct_h, ct_l, wqc_h, wqc_l, b_qkv_c, nullptr, nullptr, nullptr, qkc_h, qkc_l, MC, NCC,
        MY0, 0, DD, 3 * DD);
    // #5-#7: remaining weight pairs
    wconv2_kernel<<<dim3(DD / 32, DD / 32, 2),   wb>>>(W_proj, wp_h, wp_l, W_proj_c, wpc_h, wpc_l, DD, DD);
    wconv2_kernel<<<dim3(DFF_ / 32, DD / 32, 2), wb>>>(W_fc1, w1_h, w1_l, W_fc1_c, w1c_h, w1c_l, DD, DFF_);
    wconv2_kernel<<<dim3(DD / 32, DFF_ / 32, 2), wb>>>(W_fc2, w2_h, w2_l, W_fc2_c, w2c_h, w2c_l, DFF_, DD);
    // #8: mma flash attention
    attn_mma<<<dim3(ANCH, HH, BB), 256, ASM_TOT>>>(qk_h, qk_l, qkc_h, qkc_l, ax_h, ax_l, ac_h, ac_l);
    // #9: merged proj + gated residual (g_msa @ 2D)
    mma_gemm<2><<<dim3(DD / 128, GY), 256, GSM_TOTAL>>>(
        ax_h, ax_l, wp_h, wp_l, b_proj, x, ada, x1, nullptr, nullptr, MX, NN,
        ac_h, ac_l, wpc_h, wpc_l, b_proj_c, cond, ada_c, c1, nullptr, nullptr, MC, NCC,
        MY0, 2 * DD, DD, DD);
    // #10: LN+mod (MLP), merged
    ln2_kernel<<<MX + MC, 256>>>(x1, c1, ada, ada_c, xt_h, xt_l, ct_h, ct_l, 3 * DD, 4 * DD);
    // #11: merged fc1 + GELU -> split bf16
    mma_gemm<1><<<dim3(DFF_ / 128, GY), 256, GSM_TOTAL>>>(
        xt_h, xt_l, w1_h, w1_l, b_fc1, nullptr, nullptr, nullptr, h_h, h_l, MX, NN,
        ct_h, ct_l, w1c_h, w1c_l, b_fc1_c, nullptr, nullptr, nullptr, hc_h, hc_l, MC, NCC,
        MY0, 0, DD, DFF_);
    // #12: merged fc2 + gated residual (g_mlp @ 5D) -> final outputs
    mma_gemm<2><<<dim3(DD / 128, GY), 256, GSM_TOTAL>>>(
        h_h, h_l, w2_h, w2_l, b_fc2, x1, ada, out_x, nullptr, nullptr, MX, NN,
        hc_h, hc_l, w2c_h, w2c_l, b_fc2_c, c1, ada_c, out_c, nullptr, nullptr, MC, NCC,
        MY0, 5 * DD, DFF_, DD);
}